// round 7
// baseline (speedup 1.0000x reference)
#include <cuda_runtime.h>
#include <cuda_bf16.h>
#include <cstdint>

// Problem constants
#define NB   32
#define NN   4096
#define DM   64
#define DIN  65
#define MROWS (NB*DM)      // 2048
#define KDIM  (2*NN)       // 8192

// Scratch (device globals — allocation-free rule)
__device__ __align__(1024) __nv_bfloat16 g_Yb[(size_t)MROWS * KDIM];  // 32 MiB
__device__ __align__(1024) __nv_bfloat16 g_adjb[(size_t)2 * NN * NN]; // 64 MiB
__device__ __align__(1024) float         g_G[(size_t)MROWS * NN];     // 32 MiB

// ---------------------------------------------------------------------------
// helpers
// ---------------------------------------------------------------------------
__device__ __forceinline__ uint32_t smem_u32(const void* p) {
    uint32_t a;
    asm("{ .reg .u64 t; cvta.to.shared.u64 t, %1; cvt.u32.u64 %0, t; }" : "=r"(a) : "l"(p));
    return a;
}
__device__ __forceinline__ void cp16(uint32_t dst, const void* src) {
    asm volatile("cp.async.cg.shared.global [%0], [%1], 16;" :: "r"(dst), "l"(src));
}
// SW128 swizzle for 128B rows: off ^ ((off>>3)&0x70)
__device__ __forceinline__ uint32_t sw128(uint32_t off) {
    return off ^ ((off >> 3) & 0x70);
}
__device__ __forceinline__ void ldsm4(uint32_t& r0, uint32_t& r1, uint32_t& r2,
                                      uint32_t& r3, uint32_t a) {
    asm volatile("ldmatrix.sync.aligned.m8n8.x4.shared.b16 {%0,%1,%2,%3}, [%4];"
        : "=r"(r0), "=r"(r1), "=r"(r2), "=r"(r3) : "r"(a));
}
__device__ __forceinline__ void mma16(float* d,
    uint32_t a0, uint32_t a1, uint32_t a2, uint32_t a3, uint32_t b0, uint32_t b1) {
    asm volatile("mma.sync.aligned.m16n8k16.row.col.f32.bf16.bf16.f32 "
        "{%0,%1,%2,%3},{%4,%5,%6,%7},{%8,%9},{%0,%1,%2,%3};"
        : "+f"(d[0]), "+f"(d[1]), "+f"(d[2]), "+f"(d[3])
        : "r"(a0), "r"(a1), "r"(a2), "r"(a3), "r"(b0), "r"(b1));
}

// ---------------------------------------------------------------------------
// K0: adj fp32 -> bf16 (g_adjb)
// ---------------------------------------------------------------------------
__global__ void __launch_bounds__(256) k0_conv(const float4* __restrict__ adj) {
    size_t i = (size_t)blockIdx.x * 256 + threadIdx.x;   // 8,388,608 float4s
    float4 v = adj[i];
    __nv_bfloat162 lo = __float22bfloat162_rn(make_float2(v.x, v.y));
    __nv_bfloat162 hi = __float22bfloat162_rn(make_float2(v.z, v.w));
    uint2 o;
    o.x = *reinterpret_cast<uint32_t*>(&lo);
    o.y = *reinterpret_cast<uint32_t*>(&hi);
    reinterpret_cast<uint2*>(g_adjb)[i] = o;
}

// ---------------------------------------------------------------------------
// K1: Y[(b*64+m), s*4096+v] (bf16, plain row-major)
// ---------------------------------------------------------------------------
__global__ void __launch_bounds__(128) k1_buildY(
    const float* __restrict__ x, const float* __restrict__ h,
    const float* __restrict__ Wmlp)
{
    __shared__ float sWh[128][64];
    __shared__ float sWx[128];
    const int tid = threadIdx.x;
    for (int o = tid; o < 128; o += 128) {
        int s = o >> 6, m = o & 63;
        sWx[o] = Wmlp[m * 130 + s * 65];
    }
    for (int idx = tid; idx < 128 * 64; idx += 128) {
        int o = idx >> 6, j = idx & 63;
        int s = o >> 6, m = o & 63;
        sWh[o][j] = Wmlp[m * 130 + s * 65 + 1 + j];
    }
    __syncthreads();

    const int b = blockIdx.y;
    const int v = blockIdx.x * 128 + tid;

    float hreg[64];
    const float* hb = h + (size_t)b * DM * NN + v;
#pragma unroll
    for (int j = 0; j < 64; j++) hreg[j] = hb[(size_t)j * NN];
    const float xv = x[(size_t)b * NN + v];
    const size_t rowbase = (size_t)b * 64;

#pragma unroll 1
    for (int o = 0; o < 128; o++) {
        int s = o >> 6, m = o & 63;
        float acc = sWx[o] * xv;
        const float4* w4 = reinterpret_cast<const float4*>(sWh[o]);
#pragma unroll
        for (int q = 0; q < 16; q++) {
            float4 w = w4[q];
            acc += w.x * hreg[4*q] + w.y * hreg[4*q+1]
                 + w.z * hreg[4*q+2] + w.w * hreg[4*q+3];
        }
        g_Yb[(rowbase + m) * KDIM + (size_t)s * NN + v] = __float2bfloat16_rn(acc);
    }
}

// ---------------------------------------------------------------------------
// K2: G[2048,4096] = Y @ A   (bf16 mma.sync.m16n8k16 + ldmatrix)
// CTA tile 128x256x64, 3-stage cp.async ring, 8 warps (2x4), warp tile 64x64.
// ---------------------------------------------------------------------------
#define STAGES      3
#define A_BYTES     16384           // 128 rows x 128B (k=64 bf16), SW128
#define B_BYTES     32768           // 256 rows x 128B
#define STAGE_BYTES (A_BYTES + B_BYTES)
#define K2_SMEM     (STAGES * STAGE_BYTES)   // 147456

__global__ void __launch_bounds__(256, 1) k2_gemm()
{
    extern __shared__ char smem[];
    const uint32_t sbase = smem_u32(smem);
    const int tid  = threadIdx.x;
    const int lane = tid & 31, warp = tid >> 5;
    const int wm = warp >> 2, wn = warp & 3;        // 2 x 4 warp grid
    const int bx = blockIdx.x, by = blockIdx.y;
    const int m0 = by * 128, n0 = bx * 256;

    // fragment-load lane geometry (ldmatrix.x4, no trans; TN k-major tiles)
    const int alrow = (lane & 7) + ((lane >> 3) & 1) * 8;   // A: {m0-7,m8-15}x{k0,k16}
    const int akb   = (lane >> 4) * 16;
    const int blrow = (lane & 7) + ((lane >> 4) << 3);      // B: {n0-7}x{klo,khi},{n8-15}x{klo,khi}
    const int bkb   = ((lane >> 3) & 1) * 16;
    const int xorm  = (lane & 7) << 4;                      // swizzle XOR (row&7)<<4

    float acc[4][8][4];
#pragma unroll
    for (int i = 0; i < 4; i++)
#pragma unroll
        for (int j = 0; j < 8; j++)
#pragma unroll
            for (int q = 0; q < 4; q++) acc[i][j][q] = 0.f;

    auto load_stage = [&](int st, int k) {
        const int k0 = k << 6;
        const int ssel = k0 >> 12, kv = k0 & (NN - 1);
        const uint32_t abase = sbase + st * STAGE_BYTES;
        const uint32_t bbase = abase + A_BYTES;
#pragma unroll
        for (int i = 0; i < 4; i++) {                  // A: 128 rows x 8 x 16B
            int c = i * 256 + tid;
            int row = c >> 3, col = c & 7;
            cp16(abase + sw128(row * 128 + col * 16),
                 g_Yb + (size_t)(m0 + row) * KDIM + k0 + col * 8);
        }
#pragma unroll
        for (int i = 0; i < 8; i++) {                  // B: 256 rows x 8 x 16B
            int c = i * 256 + tid;
            int row = c >> 3, col = c & 7;
            cp16(bbase + sw128(row * 128 + col * 16),
                 g_adjb + (size_t)ssel * NN * NN + (size_t)(n0 + row) * NN + kv + col * 8);
        }
    };

    load_stage(0, 0); asm volatile("cp.async.commit_group;");
    load_stage(1, 1); asm volatile("cp.async.commit_group;");

    const int NSTEP = KDIM / 64;   // 128
#pragma unroll 1
    for (int k = 0; k < NSTEP; k++) {
        asm volatile("cp.async.wait_group 1;");
        __syncthreads();
        const int st = k % STAGES;
        const uint32_t sA = sbase + st * STAGE_BYTES;
        const uint32_t sB = sA + A_BYTES;
        const uint32_t aBase = sA + (uint32_t)(wm * 64 + alrow) * 128;
        const uint32_t bBase = sB + (uint32_t)(wn * 64 + blrow) * 128;

#pragma unroll
        for (int ks = 0; ks < 4; ks++) {
            const int kb = ks * 32;
            uint32_t bf[8][2];
#pragma unroll
            for (int j = 0; j < 4; j++) {
                uint32_t r0, r1, r2, r3;
                ldsm4(r0, r1, r2, r3,
                      bBase + (uint32_t)(j * 16) * 128 + ((kb + bkb) ^ xorm));
                bf[2*j][0] = r0;   bf[2*j][1] = r1;
                bf[2*j+1][0] = r2; bf[2*j+1][1] = r3;
            }
#pragma unroll
            for (int mt = 0; mt < 4; mt++) {
                uint32_t a0, a1, a2, a3;
                ldsm4(a0, a1, a2, a3,
                      aBase + (uint32_t)(mt * 16) * 128 + ((kb + akb) ^ xorm));
#pragma unroll
                for (int nt = 0; nt < 8; nt++)
                    mma16(acc[mt][nt], a0, a1, a2, a3, bf[nt][0], bf[nt][1]);
            }
        }

        // Load for iter k+2 overwrites stage (k+2)%3, which was consumed at
        // iter k-1; the barrier at the top of iter k already ordered that.
        const int kn = k + 2;
        if (kn < NSTEP) load_stage(kn % STAGES, kn);
        asm volatile("cp.async.commit_group;");   // empty group in tail keeps semantics
    }

    // Store C tile -> g_G
    const int g = lane >> 2, t = lane & 3;
#pragma unroll
    for (int mt = 0; mt < 4; mt++) {
        const int row = m0 + wm * 64 + mt * 16 + g;
#pragma unroll
        for (int nt = 0; nt < 8; nt++) {
            const int col = n0 + wn * 64 + nt * 8 + 2 * t;
            float2 v0 = make_float2(acc[mt][nt][0], acc[mt][nt][1]);
            float2 v1 = make_float2(acc[mt][nt][2], acc[mt][nt][3]);
            *reinterpret_cast<float2*>(&g_G[(size_t)row       * NN + col]) = v0;
            *reinterpret_cast<float2*>(&g_G[(size_t)(row + 8) * NN + col]) = v1;
        }
    }
}

// ---------------------------------------------------------------------------
// K3: epilogue. Per (b,w): lin = Wlin @ [G+bmlp ; h] + blin ; PReLU ; out2 ; read
// Split-output: 2 threads per point, 32 output channels each (regs 120 -> ~60).
// ---------------------------------------------------------------------------
__global__ void __launch_bounds__(256) k3_epi(
    const float* __restrict__ h,    const float* __restrict__ Wlin,
    const float* __restrict__ blin, const float* __restrict__ bmlp,
    const float* __restrict__ Wread,const float* __restrict__ bread,
    const float* __restrict__ pa,
    float* __restrict__ out_read,   float* __restrict__ out2)
{
    __shared__ float sWT[128][64];   // sWT[in][o] = Wlin[o,in]
    __shared__ float sWr[128];
    __shared__ float sbl[64];
    __shared__ float sbm[64];
    __shared__ float sRacc[256];
    const int tid = threadIdx.x;
    for (int idx = tid; idx < 128 * 64; idx += 256) {
        int in = idx >> 6, o = idx & 63;
        sWT[in][o] = Wlin[o * 128 + in];
    }
    if (tid < 128) sWr[tid] = Wread[tid];
    if (tid < 64) { sbl[tid] = blin[tid]; sbm[tid] = bmlp[tid]; }
    __syncthreads();

    const int b    = blockIdx.y;
    const int wl   = tid & 127;          // point within tile
    const int half = tid >> 7;           // output-channel half
    const int ob   = half * 32;
    const int w    = blockIdx.x * 128 + wl;

    float lin[32];
#pragma unroll
    for (int o = 0; o < 32; o++) lin[o] = sbl[ob + o];
    float racc = 0.f;
    const float a = __ldg(pa);

    const float* Gb = g_G + (size_t)b * 64 * NN + w;
    const float* hb = h    + (size_t)b * 64 * NN + w;
    float*       o2 = out2 + (size_t)b * 128 * NN + w;

#pragma unroll 1
    for (int m = 0; m < 64; m++) {
        float gv = Gb[(size_t)m * NN] + sbm[m];
        const float4* wrow = reinterpret_cast<const float4*>(&sWT[m][ob]);
#pragma unroll
        for (int q = 0; q < 8; q++) {
            float4 wv = wrow[q];
            lin[4*q]   += wv.x * gv; lin[4*q+1] += wv.y * gv;
            lin[4*q+2] += wv.z * gv; lin[4*q+3] += wv.w * gv;
        }
    }
#pragma unroll 1
    for (int j = 0; j < 64; j++) {
        float hv = hb[(size_t)j * NN];
        if (half) {
            o2[(size_t)(64 + j) * NN] = hv;
            racc += sWr[64 + j] * hv;
        }
        const float4* wrow = reinterpret_cast<const float4*>(&sWT[64 + j][ob]);
#pragma unroll
        for (int q = 0; q < 8; q++) {
            float4 wv = wrow[q];
            lin[4*q]   += wv.x * hv; lin[4*q+1] += wv.y * hv;
            lin[4*q+2] += wv.z * hv; lin[4*q+3] += wv.w * hv;
        }
    }
#pragma unroll
    for (int o = 0; o < 32; o++) {
        float pr = lin[o] >= 0.f ? lin[o] : a * lin[o];
        o2[(size_t)(ob + o) * NN] = pr;
        racc += sWr[ob + o] * pr;
    }
    sRacc[tid] = racc;
    __syncthreads();
    if (half == 0)
        out_read[(size_t)b * NN + w] = sRacc[tid] + sRacc[tid + 128] + __ldg(bread);
}

// ---------------------------------------------------------------------------
extern "C" void kernel_launch(void* const* d_in, const int* in_sizes, int n_in,
                              void* d_out, int out_size) {
    (void)in_sizes; (void)n_in; (void)out_size;
    const float* x     = (const float*)d_in[0];
    const float* h     = (const float*)d_in[1];
    const float* adj   = (const float*)d_in[2];
    const float* Wmlp  = (const float*)d_in[3];
    const float* bmlp  = (const float*)d_in[4];
    const float* Wlin  = (const float*)d_in[5];
    const float* blin  = (const float*)d_in[6];
    const float* Wread = (const float*)d_in[7];
    const float* bread = (const float*)d_in[8];
    const float* pa    = (const float*)d_in[9];

    float* out      = (float*)d_out;
    float* out_read = out;                       // [32, 1, 4096]
    float* out2     = out + (size_t)NB * NN;     // [32, 128, 4096]

    cudaFuncSetAttribute(k2_gemm, cudaFuncAttributeMaxDynamicSharedMemorySize, K2_SMEM);

    k0_conv  <<<32768, 256>>>((const float4*)adj);
    k1_buildY<<<dim3(NN / 128, NB), 128>>>(x, h, Wmlp);
    k2_gemm  <<<dim3(NN / 256, MROWS / 128), 256, K2_SMEM>>>();
    k3_epi   <<<dim3(NN / 128, NB), 256>>>(h, Wlin, blin, bmlp, Wread, bread, pa,
                                           out_read, out2);
}

// round 8
// speedup vs baseline: 1.0712x; 1.0712x over previous
#include <cuda_runtime.h>
#include <cuda_bf16.h>
#include <cstdint>

// Problem constants
#define NB   32
#define NN   4096
#define DM   64
#define DIN  65
#define MROWS (NB*DM)      // 2048
#define KDIM  (2*NN)       // 8192

// Scratch (device globals — allocation-free rule)
__device__ __align__(1024) __nv_bfloat16 g_Yb[(size_t)MROWS * KDIM];  // 32 MiB
__device__ __align__(1024) __nv_bfloat16 g_adjb[(size_t)2 * NN * NN]; // 64 MiB
__device__ __align__(1024) float         g_G[(size_t)MROWS * NN];     // 32 MiB

// ---------------------------------------------------------------------------
// helpers
// ---------------------------------------------------------------------------
__device__ __forceinline__ uint32_t smem_u32(const void* p) {
    uint32_t a;
    asm("{ .reg .u64 t; cvta.to.shared.u64 t, %1; cvt.u32.u64 %0, t; }" : "=r"(a) : "l"(p));
    return a;
}
__device__ __forceinline__ void cp16(uint32_t dst, const void* src) {
    asm volatile("cp.async.cg.shared.global [%0], [%1], 16;" :: "r"(dst), "l"(src));
}
// SW128 swizzle for 128B rows: off ^ ((off>>3)&0x70)
__device__ __forceinline__ uint32_t sw128(uint32_t off) {
    return off ^ ((off >> 3) & 0x70);
}
__device__ __forceinline__ void ldsm4(uint32_t& r0, uint32_t& r1, uint32_t& r2,
                                      uint32_t& r3, uint32_t a) {
    asm volatile("ldmatrix.sync.aligned.m8n8.x4.shared.b16 {%0,%1,%2,%3}, [%4];"
        : "=r"(r0), "=r"(r1), "=r"(r2), "=r"(r3) : "r"(a));
}
__device__ __forceinline__ void mma16(float* d,
    uint32_t a0, uint32_t a1, uint32_t a2, uint32_t a3, uint32_t b0, uint32_t b1) {
    asm volatile("mma.sync.aligned.m16n8k16.row.col.f32.bf16.bf16.f32 "
        "{%0,%1,%2,%3},{%4,%5,%6,%7},{%8,%9},{%0,%1,%2,%3};"
        : "+f"(d[0]), "+f"(d[1]), "+f"(d[2]), "+f"(d[3])
        : "r"(a0), "r"(a1), "r"(a2), "r"(a3), "r"(b0), "r"(b1));
}

// ---------------------------------------------------------------------------
// K0: adj fp32 -> bf16 (g_adjb)
// ---------------------------------------------------------------------------
__global__ void __launch_bounds__(256) k0_conv(const float4* __restrict__ adj) {
    size_t i = (size_t)blockIdx.x * 256 + threadIdx.x;   // 8,388,608 float4s
    float4 v = adj[i];
    __nv_bfloat162 lo = __float22bfloat162_rn(make_float2(v.x, v.y));
    __nv_bfloat162 hi = __float22bfloat162_rn(make_float2(v.z, v.w));
    uint2 o;
    o.x = *reinterpret_cast<uint32_t*>(&lo);
    o.y = *reinterpret_cast<uint32_t*>(&hi);
    reinterpret_cast<uint2*>(g_adjb)[i] = o;
}

// ---------------------------------------------------------------------------
// K1: Y[(b*64+m), s*4096+v] (bf16, plain row-major)
// ---------------------------------------------------------------------------
__global__ void __launch_bounds__(128) k1_buildY(
    const float* __restrict__ x, const float* __restrict__ h,
    const float* __restrict__ Wmlp)
{
    __shared__ float sWh[128][64];
    __shared__ float sWx[128];
    const int tid = threadIdx.x;
    for (int o = tid; o < 128; o += 128) {
        int s = o >> 6, m = o & 63;
        sWx[o] = Wmlp[m * 130 + s * 65];
    }
    for (int idx = tid; idx < 128 * 64; idx += 128) {
        int o = idx >> 6, j = idx & 63;
        int s = o >> 6, m = o & 63;
        sWh[o][j] = Wmlp[m * 130 + s * 65 + 1 + j];
    }
    __syncthreads();

    const int b = blockIdx.y;
    const int v = blockIdx.x * 128 + tid;

    float hreg[64];
    const float* hb = h + (size_t)b * DM * NN + v;
#pragma unroll
    for (int j = 0; j < 64; j++) hreg[j] = hb[(size_t)j * NN];
    const float xv = x[(size_t)b * NN + v];
    const size_t rowbase = (size_t)b * 64;

#pragma unroll 1
    for (int o = 0; o < 128; o++) {
        int s = o >> 6, m = o & 63;
        float acc = sWx[o] * xv;
        const float4* w4 = reinterpret_cast<const float4*>(sWh[o]);
#pragma unroll
        for (int q = 0; q < 16; q++) {
            float4 w = w4[q];
            acc += w.x * hreg[4*q] + w.y * hreg[4*q+1]
                 + w.z * hreg[4*q+2] + w.w * hreg[4*q+3];
        }
        g_Yb[(rowbase + m) * KDIM + (size_t)s * NN + v] = __float2bfloat16_rn(acc);
    }
}

// ---------------------------------------------------------------------------
// K2: G[2048,4096] = Y @ A   (bf16 mma.sync.m16n8k16 + ldmatrix)
// CTA tile 128x128x64, 3-stage cp.async ring, 8 warps (2x4), warp tile 64x32.
// ---------------------------------------------------------------------------
#define STAGES      3
#define A_BYTES     16384           // 128 rows x 128B (k=64 bf16), SW128
#define B_BYTES     16384
#define STAGE_BYTES (A_BYTES + B_BYTES)
#define K2_SMEM     (STAGES * STAGE_BYTES)   // 98304

__global__ void __launch_bounds__(256, 2) k2_gemm()
{
    extern __shared__ char smem[];
    const uint32_t sbase = smem_u32(smem);
    const int tid  = threadIdx.x;
    const int lane = tid & 31, warp = tid >> 5;
    const int wm = warp >> 2, wn = warp & 3;        // 2 x 4 warp grid
    const int bx = blockIdx.x, by = blockIdx.y;
    const int m0 = by * 128, n0 = bx * 128;

    // fragment-load lane geometry (ldmatrix.x4, no trans; TN k-major tiles)
    const int alrow = (lane & 7) + ((lane >> 3) & 1) * 8;   // A: {m0-7,m8-15}x{k0,k16}
    const int akb   = (lane >> 4) * 16;
    const int blrow = (lane & 7) + ((lane >> 4) << 3);      // B: {n0-7},{n8-15} x {klo,khi}
    const int bkb   = ((lane >> 3) & 1) * 16;
    const int xorm  = (lane & 7) << 4;                      // swizzle XOR (row&7)<<4

    float acc[4][4][4];
#pragma unroll
    for (int i = 0; i < 4; i++)
#pragma unroll
        for (int j = 0; j < 4; j++)
#pragma unroll
            for (int q = 0; q < 4; q++) acc[i][j][q] = 0.f;

    auto load_stage = [&](int st, int k) {
        const int k0 = k << 6;
        const int ssel = k0 >> 12, kv = k0 & (NN - 1);
        const uint32_t abase = sbase + st * STAGE_BYTES;
        const uint32_t bbase = abase + A_BYTES;
#pragma unroll
        for (int i = 0; i < 4; i++) {                  // A: 128 rows x 8 x 16B
            int c = i * 256 + tid;
            int row = c >> 3, col = c & 7;
            cp16(abase + sw128(row * 128 + col * 16),
                 g_Yb + (size_t)(m0 + row) * KDIM + k0 + col * 8);
        }
#pragma unroll
        for (int i = 0; i < 4; i++) {                  // B: 128 rows x 8 x 16B
            int c = i * 256 + tid;
            int row = c >> 3, col = c & 7;
            cp16(bbase + sw128(row * 128 + col * 16),
                 g_adjb + (size_t)ssel * NN * NN + (size_t)(n0 + row) * NN + kv + col * 8);
        }
    };

    load_stage(0, 0); asm volatile("cp.async.commit_group;");
    load_stage(1, 1); asm volatile("cp.async.commit_group;");

    const int NSTEP = KDIM / 64;   // 128
#pragma unroll 1
    for (int k = 0; k < NSTEP; k++) {
        asm volatile("cp.async.wait_group 1;");
        __syncthreads();
        const int st = k % STAGES;
        const uint32_t sA = sbase + st * STAGE_BYTES;
        const uint32_t sB = sA + A_BYTES;
        const uint32_t aBase = sA + (uint32_t)(wm * 64 + alrow) * 128;
        const uint32_t bBase = sB + (uint32_t)(wn * 32 + blrow) * 128;

#pragma unroll
        for (int ks = 0; ks < 4; ks++) {
            const int kb = ks * 32;
            uint32_t bf[4][2];
#pragma unroll
            for (int j = 0; j < 2; j++) {
                uint32_t r0, r1, r2, r3;
                ldsm4(r0, r1, r2, r3,
                      bBase + (uint32_t)(j * 16) * 128 + ((kb + bkb) ^ xorm));
                bf[2*j][0] = r0;   bf[2*j][1] = r1;
                bf[2*j+1][0] = r2; bf[2*j+1][1] = r3;
            }
#pragma unroll
            for (int mt = 0; mt < 4; mt++) {
                uint32_t a0, a1, a2, a3;
                ldsm4(a0, a1, a2, a3,
                      aBase + (uint32_t)(mt * 16) * 128 + ((kb + akb) ^ xorm));
#pragma unroll
                for (int nt = 0; nt < 4; nt++)
                    mma16(acc[mt][nt], a0, a1, a2, a3, bf[nt][0], bf[nt][1]);
            }
        }

        // Load for iter k+2 overwrites stage (k+2)%3, consumed at iter k-1;
        // the barrier at the top of iter k already ordered that.
        const int kn = k + 2;
        if (kn < NSTEP) load_stage(kn % STAGES, kn);
        asm volatile("cp.async.commit_group;");   // empty group in tail keeps semantics
    }

    // Store C tile -> g_G
    const int g = lane >> 2, t = lane & 3;
#pragma unroll
    for (int mt = 0; mt < 4; mt++) {
        const int row = m0 + wm * 64 + mt * 16 + g;
#pragma unroll
        for (int nt = 0; nt < 4; nt++) {
            const int col = n0 + wn * 32 + nt * 8 + 2 * t;
            float2 v0 = make_float2(acc[mt][nt][0], acc[mt][nt][1]);
            float2 v1 = make_float2(acc[mt][nt][2], acc[mt][nt][3]);
            *reinterpret_cast<float2*>(&g_G[(size_t)row       * NN + col]) = v0;
            *reinterpret_cast<float2*>(&g_G[(size_t)(row + 8) * NN + col]) = v1;
        }
    }
}

// ---------------------------------------------------------------------------
// K3: epilogue. Per (b,w): lin = Wlin @ [G+bmlp ; h] + blin ; PReLU ; out2 ; read
// 2 points + 32 channels per thread; prefetched G/h rows break the
// LDG -> 64-FMA serial dependency (R7's stall source).
// ---------------------------------------------------------------------------
__global__ void __launch_bounds__(256) k3_epi(
    const float* __restrict__ h,    const float* __restrict__ Wlin,
    const float* __restrict__ blin, const float* __restrict__ bmlp,
    const float* __restrict__ Wread,const float* __restrict__ bread,
    const float* __restrict__ pa,
    float* __restrict__ out_read,   float* __restrict__ out2)
{
    __shared__ float sWT[128][64];   // sWT[in][o] = Wlin[o,in]
    __shared__ float sWr[128];
    __shared__ float sbl[64];
    __shared__ float sbm[64];
    __shared__ float sR0[256];
    __shared__ float sR1[256];
    const int tid = threadIdx.x;
    for (int idx = tid; idx < 128 * 64; idx += 256) {
        int in = idx >> 6, o = idx & 63;
        sWT[in][o] = Wlin[o * 128 + in];
    }
    if (tid < 128) sWr[tid] = Wread[tid];
    if (tid < 64) { sbl[tid] = blin[tid]; sbm[tid] = bmlp[tid]; }
    __syncthreads();

    const int b    = blockIdx.y;
    const int wl   = tid & 127;          // point within tile
    const int half = tid >> 7;           // output-channel half
    const int ob   = half * 32;
    const int w0   = blockIdx.x * 256 + wl;     // second point = w0 + 128

    float lin0[32], lin1[32];
#pragma unroll
    for (int o = 0; o < 32; o++) { lin0[o] = sbl[ob + o]; lin1[o] = lin0[o]; }
    const float a = __ldg(pa);

    const float* Gb = g_G + (size_t)b * 64 * NN + w0;
    const float* hb = h    + (size_t)b * 64 * NN + w0;
    float*       o2 = out2 + (size_t)b * 128 * NN + w0;

    float g0 = Gb[0], g1 = Gb[128];
#pragma unroll 1
    for (int m = 0; m < 64; m++) {
        const float gv0 = g0 + sbm[m], gv1 = g1 + sbm[m];
        if (m < 63) { g0 = Gb[(size_t)(m + 1) * NN]; g1 = Gb[(size_t)(m + 1) * NN + 128]; }
        const float4* wrow = reinterpret_cast<const float4*>(&sWT[m][ob]);
#pragma unroll
        for (int q = 0; q < 8; q++) {
            float4 wv = wrow[q];
            lin0[4*q]   += wv.x * gv0; lin0[4*q+1] += wv.y * gv0;
            lin0[4*q+2] += wv.z * gv0; lin0[4*q+3] += wv.w * gv0;
            lin1[4*q]   += wv.x * gv1; lin1[4*q+1] += wv.y * gv1;
            lin1[4*q+2] += wv.z * gv1; lin1[4*q+3] += wv.w * gv1;
        }
    }

    float racc0 = 0.f, racc1 = 0.f;
    float h0 = hb[0], h1 = hb[128];
#pragma unroll 1
    for (int j = 0; j < 64; j++) {
        const float hv0 = h0, hv1 = h1;
        if (j < 63) { h0 = hb[(size_t)(j + 1) * NN]; h1 = hb[(size_t)(j + 1) * NN + 128]; }
        if (half) {
            o2[(size_t)(64 + j) * NN]       = hv0;
            o2[(size_t)(64 + j) * NN + 128] = hv1;
            racc0 += sWr[64 + j] * hv0;
            racc1 += sWr[64 + j] * hv1;
        }
        const float4* wrow = reinterpret_cast<const float4*>(&sWT[64 + j][ob]);
#pragma unroll
        for (int q = 0; q < 8; q++) {
            float4 wv = wrow[q];
            lin0[4*q]   += wv.x * hv0; lin0[4*q+1] += wv.y * hv0;
            lin0[4*q+2] += wv.z * hv0; lin0[4*q+3] += wv.w * hv0;
            lin1[4*q]   += wv.x * hv1; lin1[4*q+1] += wv.y * hv1;
            lin1[4*q+2] += wv.z * hv1; lin1[4*q+3] += wv.w * hv1;
        }
    }
#pragma unroll
    for (int o = 0; o < 32; o++) {
        float pr0 = lin0[o] >= 0.f ? lin0[o] : a * lin0[o];
        float pr1 = lin1[o] >= 0.f ? lin1[o] : a * lin1[o];
        o2[(size_t)(ob + o) * NN]       = pr0;
        o2[(size_t)(ob + o) * NN + 128] = pr1;
        racc0 += sWr[ob + o] * pr0;
        racc1 += sWr[ob + o] * pr1;
    }
    sR0[tid] = racc0;
    sR1[tid] = racc1;
    __syncthreads();
    if (half == 0) {
        const float br = __ldg(bread);
        out_read[(size_t)b * NN + w0]       = sR0[tid] + sR0[tid + 128] + br;
        out_read[(size_t)b * NN + w0 + 128] = sR1[tid] + sR1[tid + 128] + br;
    }
}

// ---------------------------------------------------------------------------
extern "C" void kernel_launch(void* const* d_in, const int* in_sizes, int n_in,
                              void* d_out, int out_size) {
    (void)in_sizes; (void)n_in; (void)out_size;
    const float* x     = (const float*)d_in[0];
    const float* h     = (const float*)d_in[1];
    const float* adj   = (const float*)d_in[2];
    const float* Wmlp  = (const float*)d_in[3];
    const float* bmlp  = (const float*)d_in[4];
    const float* Wlin  = (const float*)d_in[5];
    const float* blin  = (const float*)d_in[6];
    const float* Wread = (const float*)d_in[7];
    const float* bread = (const float*)d_in[8];
    const float* pa    = (const float*)d_in[9];

    float* out      = (float*)d_out;
    float* out_read = out;                       // [32, 1, 4096]
    float* out2     = out + (size_t)NB * NN;     // [32, 128, 4096]

    cudaFuncSetAttribute(k2_gemm, cudaFuncAttributeMaxDynamicSharedMemorySize, K2_SMEM);

    k0_conv  <<<32768, 256>>>((const float4*)adj);
    k1_buildY<<<dim3(NN / 128, NB), 128>>>(x, h, Wmlp);
    k2_gemm  <<<dim3(NN / 128, MROWS / 128), 256, K2_SMEM>>>();
    k3_epi   <<<dim3(NN / 256, NB), 256>>>(h, Wlin, blin, bmlp, Wread, bread, pa,
                                           out_read, out2);
}

// round 13
// speedup vs baseline: 1.1149x; 1.0408x over previous
#include <cuda_runtime.h>
#include <cuda_bf16.h>
#include <cstdint>

// Problem constants
#define NB   32
#define NN   4096
#define DM   64
#define DIN  65
#define MROWS (NB*DM)      // 2048
#define KDIM  (2*NN)       // 8192

// Scratch (device globals — allocation-free rule)
__device__ __align__(1024) __nv_bfloat16 g_Yb[(size_t)MROWS * KDIM];  // 32 MiB
__device__ __align__(1024) __nv_bfloat16 g_adjb[(size_t)2 * NN * NN]; // 64 MiB
__device__ __align__(1024) float         g_G[(size_t)MROWS * NN];     // 32 MiB (bmlp pre-added)

// ---------------------------------------------------------------------------
// helpers
// ---------------------------------------------------------------------------
__device__ __forceinline__ uint32_t smem_u32(const void* p) {
    uint32_t a;
    asm("{ .reg .u64 t; cvta.to.shared.u64 t, %1; cvt.u32.u64 %0, t; }" : "=r"(a) : "l"(p));
    return a;
}
__device__ __forceinline__ void cp16(uint32_t dst, const void* src) {
    asm volatile("cp.async.cg.shared.global [%0], [%1], 16;" :: "r"(dst), "l"(src));
}
// SW128 swizzle for 128B rows: off ^ ((off>>3)&0x70)
__device__ __forceinline__ uint32_t sw128(uint32_t off) {
    return off ^ ((off >> 3) & 0x70);
}
__device__ __forceinline__ void ldsm4(uint32_t& r0, uint32_t& r1, uint32_t& r2,
                                      uint32_t& r3, uint32_t a) {
    asm volatile("ldmatrix.sync.aligned.m8n8.x4.shared.b16 {%0,%1,%2,%3}, [%4];"
        : "=r"(r0), "=r"(r1), "=r"(r2), "=r"(r3) : "r"(a));
}
__device__ __forceinline__ void mma16(float* d,
    uint32_t a0, uint32_t a1, uint32_t a2, uint32_t a3, uint32_t b0, uint32_t b1) {
    asm volatile("mma.sync.aligned.m16n8k16.row.col.f32.bf16.bf16.f32 "
        "{%0,%1,%2,%3},{%4,%5,%6,%7},{%8,%9},{%0,%1,%2,%3};"
        : "+f"(d[0]), "+f"(d[1]), "+f"(d[2]), "+f"(d[3])
        : "r"(a0), "r"(a1), "r"(a2), "r"(a3), "r"(b0), "r"(b1));
}

// ---------------------------------------------------------------------------
// K0: adj fp32 -> bf16 (g_adjb)
// ---------------------------------------------------------------------------
__global__ void __launch_bounds__(256) k0_conv(const float4* __restrict__ adj) {
    size_t i = (size_t)blockIdx.x * 256 + threadIdx.x;   // 8,388,608 float4s
    float4 v = adj[i];
    __nv_bfloat162 lo = __float22bfloat162_rn(make_float2(v.x, v.y));
    __nv_bfloat162 hi = __float22bfloat162_rn(make_float2(v.z, v.w));
    uint2 o;
    o.x = *reinterpret_cast<uint32_t*>(&lo);
    o.y = *reinterpret_cast<uint32_t*>(&hi);
    reinterpret_cast<uint2*>(g_adjb)[i] = o;
}

// ---------------------------------------------------------------------------
// K1: Y[(b*64+m), s*4096+v] (bf16, plain row-major)
// ---------------------------------------------------------------------------
__global__ void __launch_bounds__(128) k1_buildY(
    const float* __restrict__ x, const float* __restrict__ h,
    const float* __restrict__ Wmlp)
{
    __shared__ float sWh[128][64];
    __shared__ float sWx[128];
    const int tid = threadIdx.x;
    for (int o = tid; o < 128; o += 128) {
        int s = o >> 6, m = o & 63;
        sWx[o] = Wmlp[m * 130 + s * 65];
    }
    for (int idx = tid; idx < 128 * 64; idx += 128) {
        int o = idx >> 6, j = idx & 63;
        int s = o >> 6, m = o & 63;
        sWh[o][j] = Wmlp[m * 130 + s * 65 + 1 + j];
    }
    __syncthreads();

    const int b = blockIdx.y;
    const int v = blockIdx.x * 128 + tid;

    float hreg[64];
    const float* hb = h + (size_t)b * DM * NN + v;
#pragma unroll
    for (int j = 0; j < 64; j++) hreg[j] = hb[(size_t)j * NN];
    const float xv = x[(size_t)b * NN + v];
    const size_t rowbase = (size_t)b * 64;

#pragma unroll 1
    for (int o = 0; o < 128; o++) {
        int s = o >> 6, m = o & 63;
        float acc = sWx[o] * xv;
        const float4* w4 = reinterpret_cast<const float4*>(sWh[o]);
#pragma unroll
        for (int q = 0; q < 16; q++) {
            float4 w = w4[q];
            acc += w.x * hreg[4*q] + w.y * hreg[4*q+1]
                 + w.z * hreg[4*q+2] + w.w * hreg[4*q+3];
        }
        g_Yb[(rowbase + m) * KDIM + (size_t)s * NN + v] = __float2bfloat16_rn(acc);
    }
}

// ---------------------------------------------------------------------------
// K2: G[2048,4096] = Y @ A   (bf16 mma.sync.m16n8k16 + ldmatrix)
// CTA tile 128x128x64, 3-stage cp.async ring, 8 warps (2x4), warp tile 64x32.
// Loads for iter k+2 issue BEFORE compute of iter k (overlap).
// Stores G + bmlp[m] (bias folded here, exact fp32).
// ---------------------------------------------------------------------------
#define STAGES      3
#define A_BYTES     16384           // 128 rows x 128B (k=64 bf16), SW128
#define B_BYTES     16384
#define STAGE_BYTES (A_BYTES + B_BYTES)
#define K2_SMEM     (STAGES * STAGE_BYTES)   // 98304

__global__ void __launch_bounds__(256, 2) k2_gemm(const float* __restrict__ bmlp)
{
    extern __shared__ char smem[];
    __shared__ float sbm[64];
    const uint32_t sbase = smem_u32(smem);
    const int tid  = threadIdx.x;
    const int lane = tid & 31, warp = tid >> 5;
    const int wm = warp >> 2, wn = warp & 3;        // 2 x 4 warp grid
    const int bx = blockIdx.x, by = blockIdx.y;
    const int m0 = by * 128, n0 = bx * 128;

    if (tid < 64) sbm[tid] = bmlp[tid];

    // fragment-load lane geometry (ldmatrix.x4, no trans; TN k-major tiles)
    const int alrow = (lane & 7) + ((lane >> 3) & 1) * 8;   // A: {m0-7,m8-15}x{k0,k16}
    const int akb   = (lane >> 4) * 16;
    const int blrow = (lane & 7) + ((lane >> 4) << 3);      // B: {n0-7},{n8-15} x {klo,khi}
    const int bkb   = ((lane >> 3) & 1) * 16;
    const int xorm  = (lane & 7) << 4;                      // swizzle XOR (row&7)<<4

    float acc[4][4][4];
#pragma unroll
    for (int i = 0; i < 4; i++)
#pragma unroll
        for (int j = 0; j < 4; j++)
#pragma unroll
            for (int q = 0; q < 4; q++) acc[i][j][q] = 0.f;

    auto load_stage = [&](int st, int k) {
        const int k0 = k << 6;
        const int ssel = k0 >> 12, kv = k0 & (NN - 1);
        const uint32_t abase = sbase + st * STAGE_BYTES;
        const uint32_t bbase = abase + A_BYTES;
#pragma unroll
        for (int i = 0; i < 4; i++) {                  // A: 128 rows x 8 x 16B
            int c = i * 256 + tid;
            int row = c >> 3, col = c & 7;
            cp16(abase + sw128(row * 128 + col * 16),
                 g_Yb + (size_t)(m0 + row) * KDIM + k0 + col * 8);
        }
#pragma unroll
        for (int i = 0; i < 4; i++) {                  // B: 128 rows x 8 x 16B
            int c = i * 256 + tid;
            int row = c >> 3, col = c & 7;
            cp16(bbase + sw128(row * 128 + col * 16),
                 g_adjb + (size_t)ssel * NN * NN + (size_t)(n0 + row) * NN + kv + col * 8);
        }
    };

    load_stage(0, 0); asm volatile("cp.async.commit_group;");
    load_stage(1, 1); asm volatile("cp.async.commit_group;");

    const int NSTEP = KDIM / 64;   // 128
#pragma unroll 1
    for (int k = 0; k < NSTEP; k++) {
        asm volatile("cp.async.wait_group 1;");
        __syncthreads();

        // Issue next-stage loads FIRST: stage (k+2)%3 was last read at iter
        // k-1, which the barrier above already ordered. Compute below then
        // overlaps the cp.async latency.
        const int kn = k + 2;
        if (kn < NSTEP) load_stage(kn % STAGES, kn);
        asm volatile("cp.async.commit_group;");

        const int st = k % STAGES;
        const uint32_t sA = sbase + st * STAGE_BYTES;
        const uint32_t sB = sA + A_BYTES;
        const uint32_t aBase = sA + (uint32_t)(wm * 64 + alrow) * 128;
        const uint32_t bBase = sB + (uint32_t)(wn * 32 + blrow) * 128;

#pragma unroll
        for (int ks = 0; ks < 4; ks++) {
            const int kb = ks * 32;
            uint32_t bf[4][2];
#pragma unroll
            for (int j = 0; j < 2; j++) {
                uint32_t r0, r1, r2, r3;
                ldsm4(r0, r1, r2, r3,
                      bBase + (uint32_t)(j * 16) * 128 + ((kb + bkb) ^ xorm));
                bf[2*j][0] = r0;   bf[2*j][1] = r1;
                bf[2*j+1][0] = r2; bf[2*j+1][1] = r3;
            }
#pragma unroll
            for (int mt = 0; mt < 4; mt++) {
                uint32_t a0, a1, a2, a3;
                ldsm4(a0, a1, a2, a3,
                      aBase + (uint32_t)(mt * 16) * 128 + ((kb + akb) ^ xorm));
#pragma unroll
                for (int nt = 0; nt < 4; nt++)
                    mma16(acc[mt][nt], a0, a1, a2, a3, bf[nt][0], bf[nt][1]);
            }
        }
    }

    // Store C tile -> g_G (+ bmlp bias, folded exactly in fp32)
    const int g = lane >> 2, t = lane & 3;
#pragma unroll
    for (int mt = 0; mt < 4; mt++) {
        const int row = m0 + wm * 64 + mt * 16 + g;
        const float b0 = sbm[row & 63], b1 = sbm[(row + 8) & 63];
#pragma unroll
        for (int nt = 0; nt < 4; nt++) {
            const int col = n0 + wn * 32 + nt * 8 + 2 * t;
            float2 v0 = make_float2(acc[mt][nt][0] + b0, acc[mt][nt][1] + b0);
            float2 v1 = make_float2(acc[mt][nt][2] + b1, acc[mt][nt][3] + b1);
            *reinterpret_cast<float2*>(&g_G[(size_t)row       * NN + col]) = v0;
            *reinterpret_cast<float2*>(&g_G[(size_t)(row + 8) * NN + col]) = v1;
        }
    }
}

// ---------------------------------------------------------------------------
// K3: epilogue. Per (b,w): lin = Wlin @ [G' ; h] + blin ; PReLU ; out2 ; read
// (G' already has bmlp folded.) Inputs staged in smem via cp.async
// double-buffer (4 chunks of 32 rows x 256 points) — no strided LDG in the
// compute loop. 512 threads = 256 points x 2 channel-halves.
// ---------------------------------------------------------------------------
// dynamic smem layout (floats):
#define K3_OFF_WT   0        // sWT[128][64]  (sWT[in][o] = Wlin[o][in])
#define K3_OFF_WR   8192     // sWr[128]
#define K3_OFF_BL   8320     // sbl[64]
#define K3_OFF_R    8384     // sR[512]
#define K3_OFF_BUF  8896     // sBuf[2][32][256]
#define K3_FLOATS   (K3_OFF_BUF + 2*32*256)     // 25280
#define K3_SMEM     (K3_FLOATS * 4)             // 101120 bytes

__global__ void __launch_bounds__(512, 2) k3_epi(
    const float* __restrict__ h,    const float* __restrict__ Wlin,
    const float* __restrict__ blin,
    const float* __restrict__ Wread,const float* __restrict__ bread,
    const float* __restrict__ pa,
    float* __restrict__ out_read,   float* __restrict__ out2)
{
    extern __shared__ float sm[];
    const uint32_t sbase = smem_u32(sm);
    const int tid  = threadIdx.x;
    const int wl   = tid & 255;          // point within tile
    const int half = tid >> 8;           // output-channel half
    const int ob   = half * 32;
    const int b    = blockIdx.y;
    const int wbase = blockIdx.x * 256;
    const int w    = wbase + wl;

    // weight / bias staging
    for (int idx = tid; idx < 128 * 64; idx += 512) {
        int in = idx >> 6, o = idx & 63;
        sm[K3_OFF_WT + idx] = Wlin[o * 128 + in];
    }
    if (tid < 128) sm[K3_OFF_WR + tid] = Wread[tid];
    if (tid < 64)  sm[K3_OFF_BL + tid] = blin[tid];

    const float* srcG = g_G + (size_t)b * 64 * NN + wbase;
    const float* srcH = h   + (size_t)b * 64 * NN + wbase;

    auto load_chunk = [&](int c) {
        const float* src = (c < 2) ? srcG + (size_t)(c * 32) * NN
                                   : srcH + (size_t)((c - 2) * 32) * NN;
        const uint32_t dbase = sbase + (uint32_t)(K3_OFF_BUF + (c & 1) * 8192) * 4u;
#pragma unroll
        for (int i = 0; i < 4; i++) {
            int idx = i * 512 + tid;           // 2048 x 16B per chunk
            int row = idx >> 6, c16 = idx & 63;
            cp16(dbase + (uint32_t)(row * 256 + c16 * 4) * 4u,
                 src + (size_t)row * NN + c16 * 4);
        }
    };

    load_chunk(0); asm volatile("cp.async.commit_group;");

    float lin[32];
#pragma unroll
    for (int o = 0; o < 32; o++) lin[o] = 0.f;
    float racc = 0.f;
    const float a = __ldg(pa);
    float* o2 = out2 + (size_t)b * 128 * NN + w;

#pragma unroll 1
    for (int c = 0; c < 4; c++) {
        if (c < 3) load_chunk(c + 1);
        asm volatile("cp.async.commit_group;");
        if (c < 3) asm volatile("cp.async.wait_group 1;");
        else       asm volatile("cp.async.wait_group 0;");
        __syncthreads();

        const float* bb = sm + K3_OFF_BUF + (c & 1) * 8192 + wl;   // row stride 256
        const int ib = c * 32;
#pragma unroll 1
        for (int j = 0; j < 32; j++) {
            const float v = bb[j * 256];
            const int row = ib + j;
            if (c >= 2 && half) {
                o2[(size_t)row * NN] = v;                 // h-copy (rows 64..127)
                racc += sm[K3_OFF_WR + row] * v;
            }
            const float4* wr = reinterpret_cast<const float4*>(sm + K3_OFF_WT + row * 64 + ob);
#pragma unroll
            for (int q = 0; q < 8; q++) {
                float4 wv = wr[q];
                lin[4*q]   += wv.x * v; lin[4*q+1] += wv.y * v;
                lin[4*q+2] += wv.z * v; lin[4*q+3] += wv.w * v;
            }
        }
        __syncthreads();   // all reads of buf (c&1) done before overwrite at c+2
    }

#pragma unroll
    for (int o = 0; o < 32; o++) {
        const float L = lin[o] + sm[K3_OFF_BL + ob + o];
        const float pr = L >= 0.f ? L : a * L;
        o2[(size_t)(ob + o) * NN] = pr;
        racc += sm[K3_OFF_WR + ob + o] * pr;
    }
    sm[K3_OFF_R + tid] = racc;
    __syncthreads();
    if (half == 0)
        out_read[(size_t)b * NN + w] =
            sm[K3_OFF_R + tid] + sm[K3_OFF_R + tid + 256] + __ldg(bread);
}

// ---------------------------------------------------------------------------
extern "C" void kernel_launch(void* const* d_in, const int* in_sizes, int n_in,
                              void* d_out, int out_size) {
    (void)in_sizes; (void)n_in; (void)out_size;
    const float* x     = (const float*)d_in[0];
    const float* h     = (const float*)d_in[1];
    const float* adj   = (const float*)d_in[2];
    const float* Wmlp  = (const float*)d_in[3];
    const float* bmlp  = (const float*)d_in[4];
    const float* Wlin  = (const float*)d_in[5];
    const float* blin  = (const float*)d_in[6];
    const float* Wread = (const float*)d_in[7];
    const float* bread = (const float*)d_in[8];
    const float* pa    = (const float*)d_in[9];

    float* out      = (float*)d_out;
    float* out_read = out;                       // [32, 1, 4096]
    float* out2     = out + (size_t)NB * NN;     // [32, 128, 4096]

    cudaFuncSetAttribute(k2_gemm, cudaFuncAttributeMaxDynamicSharedMemorySize, K2_SMEM);
    cudaFuncSetAttribute(k3_epi,  cudaFuncAttributeMaxDynamicSharedMemorySize, K3_SMEM);

    k0_conv  <<<32768, 256>>>((const float4*)adj);
    k1_buildY<<<dim3(NN / 128, NB), 128>>>(x, h, Wmlp);
    k2_gemm  <<<dim3(NN / 128, MROWS / 128), 256, K2_SMEM>>>(bmlp);
    k3_epi   <<<dim3(NN / 256, NB), 512, K3_SMEM>>>(h, Wlin, blin, Wread, bread, pa,
                                                    out_read, out2);
}

// round 14
// speedup vs baseline: 1.1313x; 1.0147x over previous
#include <cuda_runtime.h>
#include <cuda_bf16.h>
#include <cstdint>

// Problem constants
#define NB   32
#define NN   4096
#define DM   64
#define DIN  65
#define MROWS (NB*DM)      // 2048
#define KDIM  (2*NN)       // 8192

// Scratch (device globals — allocation-free rule)
__device__ __align__(1024) __nv_bfloat16 g_Yb[(size_t)MROWS * KDIM];  // 32 MiB
__device__ __align__(1024) __nv_bfloat16 g_adjb[(size_t)2 * NN * NN]; // 64 MiB
__device__ __align__(1024) float         g_G[(size_t)MROWS * NN];     // 32 MiB (bmlp pre-added)

// ---------------------------------------------------------------------------
// helpers
// ---------------------------------------------------------------------------
__device__ __forceinline__ uint32_t smem_u32(const void* p) {
    uint32_t a;
    asm("{ .reg .u64 t; cvta.to.shared.u64 t, %1; cvt.u32.u64 %0, t; }" : "=r"(a) : "l"(p));
    return a;
}
__device__ __forceinline__ void cp16(uint32_t dst, const void* src) {
    asm volatile("cp.async.cg.shared.global [%0], [%1], 16;" :: "r"(dst), "l"(src));
}
// SW128 swizzle for 128B rows: off ^ ((off>>3)&0x70)
__device__ __forceinline__ uint32_t sw128(uint32_t off) {
    return off ^ ((off >> 3) & 0x70);
}
__device__ __forceinline__ void ldsm4(uint32_t& r0, uint32_t& r1, uint32_t& r2,
                                      uint32_t& r3, uint32_t a) {
    asm volatile("ldmatrix.sync.aligned.m8n8.x4.shared.b16 {%0,%1,%2,%3}, [%4];"
        : "=r"(r0), "=r"(r1), "=r"(r2), "=r"(r3) : "r"(a));
}
__device__ __forceinline__ void mma16(float* d,
    uint32_t a0, uint32_t a1, uint32_t a2, uint32_t a3, uint32_t b0, uint32_t b1) {
    asm volatile("mma.sync.aligned.m16n8k16.row.col.f32.bf16.bf16.f32 "
        "{%0,%1,%2,%3},{%4,%5,%6,%7},{%8,%9},{%0,%1,%2,%3};"
        : "+f"(d[0]), "+f"(d[1]), "+f"(d[2]), "+f"(d[3])
        : "r"(a0), "r"(a1), "r"(a2), "r"(a3), "r"(b0), "r"(b1));
}
// packed fp32x2 ops (Blackwell dual-FP32; PTX-only, ptxas never auto-fuses)
#define FMA2(acc, a, b) \
    asm("fma.rn.f32x2 %0, %1, %2, %0;" : "+l"(acc) : "l"(a), "l"(b))
#define ADD2(d, a, b) \
    asm("add.rn.f32x2 %0, %1, %2;" : "=l"(d) : "l"(a), "l"(b))
#define PACK2(d, lo, hi) \
    asm("mov.b64 %0, {%1, %2};" : "=l"(d) : "r"(__float_as_uint(lo)), "r"(__float_as_uint(hi)))
#define UNPACK2(lo, hi, v) \
    asm("mov.b64 {%0, %1}, %2;" : "=r"(lo), "=r"(hi) : "l"(v))

// ---------------------------------------------------------------------------
// K0: adj fp32 -> bf16 (g_adjb)
// ---------------------------------------------------------------------------
__global__ void __launch_bounds__(256) k0_conv(const float4* __restrict__ adj) {
    size_t i = (size_t)blockIdx.x * 256 + threadIdx.x;   // 8,388,608 float4s
    float4 v = adj[i];
    __nv_bfloat162 lo = __float22bfloat162_rn(make_float2(v.x, v.y));
    __nv_bfloat162 hi = __float22bfloat162_rn(make_float2(v.z, v.w));
    uint2 o;
    o.x = *reinterpret_cast<uint32_t*>(&lo);
    o.y = *reinterpret_cast<uint32_t*>(&hi);
    reinterpret_cast<uint2*>(g_adjb)[i] = o;
}

// ---------------------------------------------------------------------------
// K1: Y[(b*64+m), s*4096+v] (bf16, plain row-major), f32x2 packed FMA
// ---------------------------------------------------------------------------
__global__ void __launch_bounds__(128) k1_buildY(
    const float* __restrict__ x, const float* __restrict__ h,
    const float* __restrict__ Wmlp)
{
    __shared__ float sWh[128][64];
    __shared__ float sWx[128];
    const int tid = threadIdx.x;
    for (int o = tid; o < 128; o += 128) {
        int s = o >> 6, m = o & 63;
        sWx[o] = Wmlp[m * 130 + s * 65];
    }
    for (int idx = tid; idx < 128 * 64; idx += 128) {
        int o = idx >> 6, j = idx & 63;
        int s = o >> 6, m = o & 63;
        sWh[o][j] = Wmlp[m * 130 + s * 65 + 1 + j];
    }
    __syncthreads();

    const int b = blockIdx.y;
    const int v = blockIdx.x * 128 + tid;

    // h values packed as 32 f32x2 pairs
    unsigned long long hp[32];
    const float* hb = h + (size_t)b * DM * NN + v;
#pragma unroll
    for (int j = 0; j < 32; j++) {
        float h0 = hb[(size_t)(2 * j) * NN];
        float h1 = hb[(size_t)(2 * j + 1) * NN];
        PACK2(hp[j], h0, h1);
    }
    const float xv = x[(size_t)b * NN + v];
    const size_t rowbase = (size_t)b * 64;

#pragma unroll 1
    for (int o = 0; o < 128; o++) {
        int s = o >> 6, m = o & 63;
        const ulonglong2* w2 = reinterpret_cast<const ulonglong2*>(sWh[o]);
        unsigned long long acc0 = 0ull, acc1 = 0ull;   // two chains cover FMA latency
#pragma unroll
        for (int q = 0; q < 16; q++) {
            ulonglong2 ww = w2[q];
            FMA2(acc0, ww.x, hp[2*q]);
            FMA2(acc1, ww.y, hp[2*q+1]);
        }
        unsigned long long s2; ADD2(s2, acc0, acc1);
        uint32_t lo, hi; UNPACK2(lo, hi, s2);
        float acc = fmaf(sWx[o], xv, __uint_as_float(lo) + __uint_as_float(hi));
        g_Yb[(rowbase + m) * KDIM + (size_t)s * NN + v] = __float2bfloat16_rn(acc);
    }
}

// ---------------------------------------------------------------------------
// K2: G[2048,4096] = Y @ A   (bf16 mma.sync.m16n8k16 + ldmatrix)
// CTA tile 128x128x64, 3-stage cp.async ring, 8 warps (2x4), warp tile 64x32.
// Loads for iter k+2 issue BEFORE compute of iter k (overlap).
// Stores G + bmlp[m] (bias folded here, exact fp32).
// ---------------------------------------------------------------------------
#define STAGES      3
#define A_BYTES     16384           // 128 rows x 128B (k=64 bf16), SW128
#define B_BYTES     16384
#define STAGE_BYTES (A_BYTES + B_BYTES)
#define K2_SMEM     (STAGES * STAGE_BYTES)   // 98304

__global__ void __launch_bounds__(256, 2) k2_gemm(const float* __restrict__ bmlp)
{
    extern __shared__ char smem[];
    __shared__ float sbm[64];
    const uint32_t sbase = smem_u32(smem);
    const int tid  = threadIdx.x;
    const int lane = tid & 31, warp = tid >> 5;
    const int wm = warp >> 2, wn = warp & 3;        // 2 x 4 warp grid
    const int bx = blockIdx.x, by = blockIdx.y;
    const int m0 = by * 128, n0 = bx * 128;

    if (tid < 64) sbm[tid] = bmlp[tid];

    // fragment-load lane geometry (ldmatrix.x4, no trans; TN k-major tiles)
    const int alrow = (lane & 7) + ((lane >> 3) & 1) * 8;   // A: {m0-7,m8-15}x{k0,k16}
    const int akb   = (lane >> 4) * 16;
    const int blrow = (lane & 7) + ((lane >> 4) << 3);      // B: {n0-7},{n8-15} x {klo,khi}
    const int bkb   = ((lane >> 3) & 1) * 16;
    const int xorm  = (lane & 7) << 4;                      // swizzle XOR (row&7)<<4

    float acc[4][4][4];
#pragma unroll
    for (int i = 0; i < 4; i++)
#pragma unroll
        for (int j = 0; j < 4; j++)
#pragma unroll
            for (int q = 0; q < 4; q++) acc[i][j][q] = 0.f;

    auto load_stage = [&](int st, int k) {
        const int k0 = k << 6;
        const int ssel = k0 >> 12, kv = k0 & (NN - 1);
        const uint32_t abase = sbase + st * STAGE_BYTES;
        const uint32_t bbase = abase + A_BYTES;
#pragma unroll
        for (int i = 0; i < 4; i++) {                  // A: 128 rows x 8 x 16B
            int c = i * 256 + tid;
            int row = c >> 3, col = c & 7;
            cp16(abase + sw128(row * 128 + col * 16),
                 g_Yb + (size_t)(m0 + row) * KDIM + k0 + col * 8);
        }
#pragma unroll
        for (int i = 0; i < 4; i++) {                  // B: 128 rows x 8 x 16B
            int c = i * 256 + tid;
            int row = c >> 3, col = c & 7;
            cp16(bbase + sw128(row * 128 + col * 16),
                 g_adjb + (size_t)ssel * NN * NN + (size_t)(n0 + row) * NN + kv + col * 8);
        }
    };

    load_stage(0, 0); asm volatile("cp.async.commit_group;");
    load_stage(1, 1); asm volatile("cp.async.commit_group;");

    const int NSTEP = KDIM / 64;   // 128
#pragma unroll 1
    for (int k = 0; k < NSTEP; k++) {
        asm volatile("cp.async.wait_group 1;");
        __syncthreads();

        // Issue next-stage loads FIRST: stage (k+2)%3 was last read at iter
        // k-1, which the barrier above already ordered. Compute below then
        // overlaps the cp.async latency.
        const int kn = k + 2;
        if (kn < NSTEP) load_stage(kn % STAGES, kn);
        asm volatile("cp.async.commit_group;");

        const int st = k % STAGES;
        const uint32_t sA = sbase + st * STAGE_BYTES;
        const uint32_t sB = sA + A_BYTES;
        const uint32_t aBase = sA + (uint32_t)(wm * 64 + alrow) * 128;
        const uint32_t bBase = sB + (uint32_t)(wn * 32 + blrow) * 128;

#pragma unroll
        for (int ks = 0; ks < 4; ks++) {
            const int kb = ks * 32;
            uint32_t bf[4][2];
#pragma unroll
            for (int j = 0; j < 2; j++) {
                uint32_t r0, r1, r2, r3;
                ldsm4(r0, r1, r2, r3,
                      bBase + (uint32_t)(j * 16) * 128 + ((kb + bkb) ^ xorm));
                bf[2*j][0] = r0;   bf[2*j][1] = r1;
                bf[2*j+1][0] = r2; bf[2*j+1][1] = r3;
            }
#pragma unroll
            for (int mt = 0; mt < 4; mt++) {
                uint32_t a0, a1, a2, a3;
                ldsm4(a0, a1, a2, a3,
                      aBase + (uint32_t)(mt * 16) * 128 + ((kb + akb) ^ xorm));
#pragma unroll
                for (int nt = 0; nt < 4; nt++)
                    mma16(acc[mt][nt], a0, a1, a2, a3, bf[nt][0], bf[nt][1]);
            }
        }
    }

    // Store C tile -> g_G (+ bmlp bias, folded exactly in fp32)
    const int g = lane >> 2, t = lane & 3;
#pragma unroll
    for (int mt = 0; mt < 4; mt++) {
        const int row = m0 + wm * 64 + mt * 16 + g;
        const float b0 = sbm[row & 63], b1 = sbm[(row + 8) & 63];
#pragma unroll
        for (int nt = 0; nt < 4; nt++) {
            const int col = n0 + wn * 32 + nt * 8 + 2 * t;
            float2 v0 = make_float2(acc[mt][nt][0] + b0, acc[mt][nt][1] + b0);
            float2 v1 = make_float2(acc[mt][nt][2] + b1, acc[mt][nt][3] + b1);
            *reinterpret_cast<float2*>(&g_G[(size_t)row       * NN + col]) = v0;
            *reinterpret_cast<float2*>(&g_G[(size_t)(row + 8) * NN + col]) = v1;
        }
    }
}

// ---------------------------------------------------------------------------
// K3: epilogue. Per (b,w): lin = Wlin @ [G' ; h] + blin ; PReLU ; out2 ; read
// (G' already has bmlp folded.) Inputs staged in smem via cp.async
// double-buffer; accumulation in packed f32x2 (16 FFMA2 per input row).
// 512 threads = 256 points x 2 channel-halves.
// ---------------------------------------------------------------------------
// dynamic smem layout (floats):
#define K3_OFF_WT   0        // sWT[128][64]  (sWT[in][o] = Wlin[o][in])
#define K3_OFF_WR   8192     // sWr[128]
#define K3_OFF_BL   8320     // sbl[64]
#define K3_OFF_R    8384     // sR[512]
#define K3_OFF_BUF  8896     // sBuf[2][32][256]
#define K3_FLOATS   (K3_OFF_BUF + 2*32*256)     // 25280
#define K3_SMEM     (K3_FLOATS * 4)             // 101120 bytes

__global__ void __launch_bounds__(512, 2) k3_epi(
    const float* __restrict__ h,    const float* __restrict__ Wlin,
    const float* __restrict__ blin,
    const float* __restrict__ Wread,const float* __restrict__ bread,
    const float* __restrict__ pa,
    float* __restrict__ out_read,   float* __restrict__ out2)
{
    extern __shared__ float sm[];
    const uint32_t sbase = smem_u32(sm);
    const int tid  = threadIdx.x;
    const int wl   = tid & 255;          // point within tile
    const int half = tid >> 8;           // output-channel half
    const int ob   = half * 32;
    const int b    = blockIdx.y;
    const int wbase = blockIdx.x * 256;
    const int w    = wbase + wl;

    // weight / bias staging
    for (int idx = tid; idx < 128 * 64; idx += 512) {
        int in = idx >> 6, o = idx & 63;
        sm[K3_OFF_WT + idx] = Wlin[o * 128 + in];
    }
    if (tid < 128) sm[K3_OFF_WR + tid] = Wread[tid];
    if (tid < 64)  sm[K3_OFF_BL + tid] = blin[tid];

    const float* srcG = g_G + (size_t)b * 64 * NN + wbase;
    const float* srcH = h   + (size_t)b * 64 * NN + wbase;

    auto load_chunk = [&](int c) {
        const float* src = (c < 2) ? srcG + (size_t)(c * 32) * NN
                                   : srcH + (size_t)((c - 2) * 32) * NN;
        const uint32_t dbase = sbase + (uint32_t)(K3_OFF_BUF + (c & 1) * 8192) * 4u;
#pragma unroll
        for (int i = 0; i < 4; i++) {
            int idx = i * 512 + tid;           // 2048 x 16B per chunk
            int row = idx >> 6, c16 = idx & 63;
            cp16(dbase + (uint32_t)(row * 256 + c16 * 4) * 4u,
                 src + (size_t)row * NN + c16 * 4);
        }
    };

    load_chunk(0); asm volatile("cp.async.commit_group;");

    unsigned long long lin2[16];
#pragma unroll
    for (int o = 0; o < 16; o++) lin2[o] = 0ull;
    float racc = 0.f;
    const float a = __ldg(pa);
    float* o2 = out2 + (size_t)b * 128 * NN + w;

#pragma unroll 1
    for (int c = 0; c < 4; c++) {
        if (c < 3) load_chunk(c + 1);
        asm volatile("cp.async.commit_group;");
        if (c < 3) asm volatile("cp.async.wait_group 1;");
        else       asm volatile("cp.async.wait_group 0;");
        __syncthreads();

        const float* bb = sm + K3_OFF_BUF + (c & 1) * 8192 + wl;   // row stride 256
        const int ib = c * 32;
#pragma unroll 1
        for (int j = 0; j < 32; j++) {
            const float v = bb[j * 256];
            unsigned long long v2; PACK2(v2, v, v);
            const int row = ib + j;
            if (c >= 2 && half) {
                o2[(size_t)row * NN] = v;                 // h-copy (rows 64..127)
                racc += sm[K3_OFF_WR + row] * v;
            }
            const ulonglong2* wr =
                reinterpret_cast<const ulonglong2*>(sm + K3_OFF_WT + row * 64 + ob);
#pragma unroll
            for (int q = 0; q < 8; q++) {
                ulonglong2 ww = wr[q];
                FMA2(lin2[2*q],   ww.x, v2);
                FMA2(lin2[2*q+1], ww.y, v2);
            }
        }
        __syncthreads();   // all reads of buf (c&1) done before overwrite at c+2
    }

#pragma unroll
    for (int p = 0; p < 16; p++) {
        uint32_t ulo, uhi; UNPACK2(ulo, uhi, lin2[p]);
        const int o0 = ob + 2 * p;
        float L0 = __uint_as_float(ulo) + sm[K3_OFF_BL + o0];
        float L1 = __uint_as_float(uhi) + sm[K3_OFF_BL + o0 + 1];
        float pr0 = L0 >= 0.f ? L0 : a * L0;
        float pr1 = L1 >= 0.f ? L1 : a * L1;
        o2[(size_t)o0       * NN] = pr0;
        o2[(size_t)(o0 + 1) * NN] = pr1;
        racc += sm[K3_OFF_WR + o0] * pr0 + sm[K3_OFF_WR + o0 + 1] * pr1;
    }
    sm[K3_OFF_R + tid] = racc;
    __syncthreads();
    if (half == 0)
        out_read[(size_t)b * NN + w] =
            sm[K3_OFF_R + tid] + sm[K3_OFF_R + tid + 256] + __ldg(bread);
}

// ---------------------------------------------------------------------------
extern "C" void kernel_launch(void* const* d_in, const int* in_sizes, int n_in,
                              void* d_out, int out_size) {
    (void)in_sizes; (void)n_in; (void)out_size;
    const float* x     = (const float*)d_in[0];
    const float* h     = (const float*)d_in[1];
    const float* adj   = (const float*)d_in[2];
    const float* Wmlp  = (const float*)d_in[3];
    const float* bmlp  = (const float*)d_in[4];
    const float* Wlin  = (const float*)d_in[5];
    const float* blin  = (const float*)d_in[6];
    const float* Wread = (const float*)d_in[7];
    const float* bread = (const float*)d_in[8];
    const float* pa    = (const float*)d_in[9];

    float* out      = (float*)d_out;
    float* out_read = out;                       // [32, 1, 4096]
    float* out2     = out + (size_t)NB * NN;     // [32, 128, 4096]

    cudaFuncSetAttribute(k2_gemm, cudaFuncAttributeMaxDynamicSharedMemorySize, K2_SMEM);
    cudaFuncSetAttribute(k3_epi,  cudaFuncAttributeMaxDynamicSharedMemorySize, K3_SMEM);

    k0_conv  <<<32768, 256>>>((const float4*)adj);
    k1_buildY<<<dim3(NN / 128, NB), 128>>>(x, h, Wmlp);
    k2_gemm  <<<dim3(NN / 128, MROWS / 128), 256, K2_SMEM>>>(bmlp);
    k3_epi   <<<dim3(NN / 256, NB), 512, K3_SMEM>>>(h, Wlin, blin, Wread, bread, pa,
                                                    out_read, out2);
}

// round 15
// speedup vs baseline: 1.3027x; 1.1515x over previous
#include <cuda_runtime.h>
#include <cuda_bf16.h>
#include <cstdint>

// Problem constants
#define NB   32
#define NN   4096
#define DM   64
#define DIN  65
#define MROWS (NB*DM)      // 2048
#define KDIM  (2*NN)       // 8192

// Scratch (device globals — allocation-free rule)
__device__ __align__(1024) __nv_bfloat16 g_Yb[(size_t)MROWS * KDIM];  // 32 MiB
__device__ __align__(1024) __nv_bfloat16 g_adjb[(size_t)2 * NN * NN]; // 64 MiB
__device__ __align__(1024) float         g_G[(size_t)MROWS * NN];     // 32 MiB (bmlp pre-added)

// ---------------------------------------------------------------------------
// helpers
// ---------------------------------------------------------------------------
__device__ __forceinline__ uint32_t smem_u32(const void* p) {
    uint32_t a;
    asm("{ .reg .u64 t; cvta.to.shared.u64 t, %1; cvt.u32.u64 %0, t; }" : "=r"(a) : "l"(p));
    return a;
}
__device__ __forceinline__ void cp16(uint32_t dst, const void* src) {
    asm volatile("cp.async.cg.shared.global [%0], [%1], 16;" :: "r"(dst), "l"(src));
}
// SW128 swizzle for 128B rows: off ^ ((off>>3)&0x70)
__device__ __forceinline__ uint32_t sw128(uint32_t off) {
    return off ^ ((off >> 3) & 0x70);
}
__device__ __forceinline__ void ldsm4(uint32_t& r0, uint32_t& r1, uint32_t& r2,
                                      uint32_t& r3, uint32_t a) {
    asm volatile("ldmatrix.sync.aligned.m8n8.x4.shared.b16 {%0,%1,%2,%3}, [%4];"
        : "=r"(r0), "=r"(r1), "=r"(r2), "=r"(r3) : "r"(a));
}
__device__ __forceinline__ void mma16(float* d,
    uint32_t a0, uint32_t a1, uint32_t a2, uint32_t a3, uint32_t b0, uint32_t b1) {
    asm volatile("mma.sync.aligned.m16n8k16.row.col.f32.bf16.bf16.f32 "
        "{%0,%1,%2,%3},{%4,%5,%6,%7},{%8,%9},{%0,%1,%2,%3};"
        : "+f"(d[0]), "+f"(d[1]), "+f"(d[2]), "+f"(d[3])
        : "r"(a0), "r"(a1), "r"(a2), "r"(a3), "r"(b0), "r"(b1));
}
// tf32 m16n8k8 mma (layouts verified in R2 kernel)
__device__ __forceinline__ void mma8(float* d,
    uint32_t a0, uint32_t a1, uint32_t a2, uint32_t a3, uint32_t b0, uint32_t b1) {
    asm volatile("mma.sync.aligned.m16n8k8.row.col.f32.tf32.tf32.f32 "
        "{%0,%1,%2,%3},{%4,%5,%6,%7},{%8,%9},{%0,%1,%2,%3};"
        : "+f"(d[0]), "+f"(d[1]), "+f"(d[2]), "+f"(d[3])
        : "r"(a0), "r"(a1), "r"(a2), "r"(a3), "r"(b0), "r"(b1));
}
__device__ __forceinline__ uint32_t f2tf(float f) {
    uint32_t u; asm("cvt.rna.tf32.f32 %0, %1;" : "=r"(u) : "f"(f)); return u;
}
// packed fp32x2 ops (Blackwell dual-FP32; PTX-only)
#define FMA2(acc, a, b) \
    asm("fma.rn.f32x2 %0, %1, %2, %0;" : "+l"(acc) : "l"(a), "l"(b))
#define ADD2(d, a, b) \
    asm("add.rn.f32x2 %0, %1, %2;" : "=l"(d) : "l"(a), "l"(b))
#define PACK2(d, lo, hi) \
    asm("mov.b64 %0, {%1, %2};" : "=l"(d) : "r"(__float_as_uint(lo)), "r"(__float_as_uint(hi)))
#define UNPACK2(lo, hi, v) \
    asm("mov.b64 {%0, %1}, %2;" : "=r"(lo), "=r"(hi) : "l"(v))

// ---------------------------------------------------------------------------
// K0: adj fp32 -> bf16 (g_adjb)
// ---------------------------------------------------------------------------
__global__ void __launch_bounds__(256) k0_conv(const float4* __restrict__ adj) {
    size_t i = (size_t)blockIdx.x * 256 + threadIdx.x;   // 8,388,608 float4s
    float4 v = adj[i];
    __nv_bfloat162 lo = __float22bfloat162_rn(make_float2(v.x, v.y));
    __nv_bfloat162 hi = __float22bfloat162_rn(make_float2(v.z, v.w));
    uint2 o;
    o.x = *reinterpret_cast<uint32_t*>(&lo);
    o.y = *reinterpret_cast<uint32_t*>(&hi);
    reinterpret_cast<uint2*>(g_adjb)[i] = o;
}

// ---------------------------------------------------------------------------
// K1: Y[(b*64+m), s*4096+v] (bf16, plain row-major), f32x2 packed FMA
// ---------------------------------------------------------------------------
__global__ void __launch_bounds__(128) k1_buildY(
    const float* __restrict__ x, const float* __restrict__ h,
    const float* __restrict__ Wmlp)
{
    __shared__ float sWh[128][64];
    __shared__ float sWx[128];
    const int tid = threadIdx.x;
    for (int o = tid; o < 128; o += 128) {
        int s = o >> 6, m = o & 63;
        sWx[o] = Wmlp[m * 130 + s * 65];
    }
    for (int idx = tid; idx < 128 * 64; idx += 128) {
        int o = idx >> 6, j = idx & 63;
        int s = o >> 6, m = o & 63;
        sWh[o][j] = Wmlp[m * 130 + s * 65 + 1 + j];
    }
    __syncthreads();

    const int b = blockIdx.y;
    const int v = blockIdx.x * 128 + tid;

    // h values packed as 32 f32x2 pairs
    unsigned long long hp[32];
    const float* hb = h + (size_t)b * DM * NN + v;
#pragma unroll
    for (int j = 0; j < 32; j++) {
        float h0 = hb[(size_t)(2 * j) * NN];
        float h1 = hb[(size_t)(2 * j + 1) * NN];
        PACK2(hp[j], h0, h1);
    }
    const float xv = x[(size_t)b * NN + v];
    const size_t rowbase = (size_t)b * 64;

#pragma unroll 1
    for (int o = 0; o < 128; o++) {
        int s = o >> 6, m = o & 63;
        const ulonglong2* w2 = reinterpret_cast<const ulonglong2*>(sWh[o]);
        unsigned long long acc0 = 0ull, acc1 = 0ull;   // two chains cover FMA latency
#pragma unroll
        for (int q = 0; q < 16; q++) {
            ulonglong2 ww = w2[q];
            FMA2(acc0, ww.x, hp[2*q]);
            FMA2(acc1, ww.y, hp[2*q+1]);
        }
        unsigned long long s2; ADD2(s2, acc0, acc1);
        uint32_t lo, hi; UNPACK2(lo, hi, s2);
        float acc = fmaf(sWx[o], xv, __uint_as_float(lo) + __uint_as_float(hi));
        g_Yb[(rowbase + m) * KDIM + (size_t)s * NN + v] = __float2bfloat16_rn(acc);
    }
}

// ---------------------------------------------------------------------------
// K2: G[2048,4096] = Y @ A   (bf16 mma.sync.m16n8k16 + ldmatrix)
// CTA tile 128x128x64, 3-stage cp.async ring, 8 warps (2x4), warp tile 64x32.
// Loads for iter k+2 issue BEFORE compute of iter k (overlap).
// Stores G + bmlp[m] (bias folded here, exact fp32).
// ---------------------------------------------------------------------------
#define STAGES      3
#define A_BYTES     16384           // 128 rows x 128B (k=64 bf16), SW128
#define B_BYTES     16384
#define STAGE_BYTES (A_BYTES + B_BYTES)
#define K2_SMEM     (STAGES * STAGE_BYTES)   // 98304

__global__ void __launch_bounds__(256, 2) k2_gemm(const float* __restrict__ bmlp)
{
    extern __shared__ char smem[];
    __shared__ float sbm[64];
    const uint32_t sbase = smem_u32(smem);
    const int tid  = threadIdx.x;
    const int lane = tid & 31, warp = tid >> 5;
    const int wm = warp >> 2, wn = warp & 3;        // 2 x 4 warp grid
    const int bx = blockIdx.x, by = blockIdx.y;
    const int m0 = by * 128, n0 = bx * 128;

    if (tid < 64) sbm[tid] = bmlp[tid];

    // fragment-load lane geometry (ldmatrix.x4, no trans; TN k-major tiles)
    const int alrow = (lane & 7) + ((lane >> 3) & 1) * 8;   // A: {m0-7,m8-15}x{k0,k16}
    const int akb   = (lane >> 4) * 16;
    const int blrow = (lane & 7) + ((lane >> 4) << 3);      // B: {n0-7},{n8-15} x {klo,khi}
    const int bkb   = ((lane >> 3) & 1) * 16;
    const int xorm  = (lane & 7) << 4;                      // swizzle XOR (row&7)<<4

    float acc[4][4][4];
#pragma unroll
    for (int i = 0; i < 4; i++)
#pragma unroll
        for (int j = 0; j < 4; j++)
#pragma unroll
            for (int q = 0; q < 4; q++) acc[i][j][q] = 0.f;

    auto load_stage = [&](int st, int k) {
        const int k0 = k << 6;
        const int ssel = k0 >> 12, kv = k0 & (NN - 1);
        const uint32_t abase = sbase + st * STAGE_BYTES;
        const uint32_t bbase = abase + A_BYTES;
#pragma unroll
        for (int i = 0; i < 4; i++) {                  // A: 128 rows x 8 x 16B
            int c = i * 256 + tid;
            int row = c >> 3, col = c & 7;
            cp16(abase + sw128(row * 128 + col * 16),
                 g_Yb + (size_t)(m0 + row) * KDIM + k0 + col * 8);
        }
#pragma unroll
        for (int i = 0; i < 4; i++) {                  // B: 128 rows x 8 x 16B
            int c = i * 256 + tid;
            int row = c >> 3, col = c & 7;
            cp16(bbase + sw128(row * 128 + col * 16),
                 g_adjb + (size_t)ssel * NN * NN + (size_t)(n0 + row) * NN + kv + col * 8);
        }
    };

    load_stage(0, 0); asm volatile("cp.async.commit_group;");
    load_stage(1, 1); asm volatile("cp.async.commit_group;");

    const int NSTEP = KDIM / 64;   // 128
#pragma unroll 1
    for (int k = 0; k < NSTEP; k++) {
        asm volatile("cp.async.wait_group 1;");
        __syncthreads();

        // Issue next-stage loads FIRST: stage (k+2)%3 was last read at iter
        // k-1, which the barrier above already ordered. Compute below then
        // overlaps the cp.async latency.
        const int kn = k + 2;
        if (kn < NSTEP) load_stage(kn % STAGES, kn);
        asm volatile("cp.async.commit_group;");

        const int st = k % STAGES;
        const uint32_t sA = sbase + st * STAGE_BYTES;
        const uint32_t sB = sA + A_BYTES;
        const uint32_t aBase = sA + (uint32_t)(wm * 64 + alrow) * 128;
        const uint32_t bBase = sB + (uint32_t)(wn * 32 + blrow) * 128;

#pragma unroll
        for (int ks = 0; ks < 4; ks++) {
            const int kb = ks * 32;
            uint32_t bf[4][2];
#pragma unroll
            for (int j = 0; j < 2; j++) {
                uint32_t r0, r1, r2, r3;
                ldsm4(r0, r1, r2, r3,
                      bBase + (uint32_t)(j * 16) * 128 + ((kb + bkb) ^ xorm));
                bf[2*j][0] = r0;   bf[2*j][1] = r1;
                bf[2*j+1][0] = r2; bf[2*j+1][1] = r3;
            }
#pragma unroll
            for (int mt = 0; mt < 4; mt++) {
                uint32_t a0, a1, a2, a3;
                ldsm4(a0, a1, a2, a3,
                      aBase + (uint32_t)(mt * 16) * 128 + ((kb + akb) ^ xorm));
#pragma unroll
                for (int nt = 0; nt < 4; nt++)
                    mma16(acc[mt][nt], a0, a1, a2, a3, bf[nt][0], bf[nt][1]);
            }
        }
    }

    // Store C tile -> g_G (+ bmlp bias, folded exactly in fp32)
    const int g = lane >> 2, t = lane & 3;
#pragma unroll
    for (int mt = 0; mt < 4; mt++) {
        const int row = m0 + wm * 64 + mt * 16 + g;
        const float b0 = sbm[row & 63], b1 = sbm[(row + 8) & 63];
#pragma unroll
        for (int nt = 0; nt < 4; nt++) {
            const int col = n0 + wn * 32 + nt * 8 + 2 * t;
            float2 v0 = make_float2(acc[mt][nt][0] + b0, acc[mt][nt][1] + b0);
            float2 v1 = make_float2(acc[mt][nt][2] + b1, acc[mt][nt][3] + b1);
            *reinterpret_cast<float2*>(&g_G[(size_t)row       * NN + col]) = v0;
            *reinterpret_cast<float2*>(&g_G[(size_t)(row + 8) * NN + col]) = v1;
        }
    }
}

// ---------------------------------------------------------------------------
// K3: tensor-core epilogue. lin[64, pts] = Wlin(tf32) @ Xcat(tf32)[128, pts],
// Xcat = [G'(fp32, bmlp folded); h]. PReLU, out2 = [pr; h], out_read.
// One CTA = 128 points of one batch. X smem [k][n] feeds tf32 B frags
// directly (scalar LDS, layouts identical to the R2-verified kernel).
// h staged once in smem: reused for MMA and the exact fp32 out2 copy.
// ---------------------------------------------------------------------------
// dynamic smem layout (floats); row stride 136 words (mod 32 == 8)
#define T_OFF_W    0                       // sW[64][136]
#define T_OFF_X    (64*136)                // sX[128][136]: rows 0-63 G, 64-127 h
#define T_OFF_RACC (T_OFF_X + 128*136)     // [128]
#define T_OFF_WR   (T_OFF_RACC + 128)      // [128]
#define T_OFF_BL   (T_OFF_WR + 128)        // [64]
#define T_FLOATS   (T_OFF_BL + 64)         // 26432
#define K3_SMEM    (T_FLOATS * 4)          // 105728 bytes

__global__ void __launch_bounds__(256, 2) k3_tc(
    const float* __restrict__ h,    const float* __restrict__ Wlin,
    const float* __restrict__ blin,
    const float* __restrict__ Wread,const float* __restrict__ bread,
    const float* __restrict__ pa,
    float* __restrict__ out_read,   float* __restrict__ out2)
{
    extern __shared__ float sm[];
    const uint32_t sbase = smem_u32(sm);
    const int tid  = threadIdx.x;
    const int lane = tid & 31, warp = tid >> 5;
    const int g = lane >> 2, t = lane & 3;
    const int wm = warp >> 2, wn = warp & 3;     // 2 x 4 warp grid over 64 x 128
    const int b  = blockIdx.y;
    const int w0 = blockIdx.x * 128;

    // ---- stage W, G, h via cp.async; scalars via plain stores ----
#pragma unroll
    for (int i = 0; i < 8; i++) {                 // W: 64 rows x 32 chunks
        int idx = i * 256 + tid;
        int m = idx >> 5, c = idx & 31;
        cp16(sbase + (uint32_t)(T_OFF_W + m * 136 + c * 4) * 4u,
             Wlin + m * 128 + c * 4);
    }
#pragma unroll
    for (int i = 0; i < 8; i++) {                 // X rows 0-63: G'
        int idx = i * 256 + tid;
        int r = idx >> 5, c = idx & 31;
        cp16(sbase + (uint32_t)(T_OFF_X + r * 136 + c * 4) * 4u,
             g_G + (size_t)(b * 64 + r) * NN + w0 + c * 4);
    }
#pragma unroll
    for (int i = 0; i < 8; i++) {                 // X rows 64-127: h
        int idx = i * 256 + tid;
        int r = idx >> 5, c = idx & 31;
        cp16(sbase + (uint32_t)(T_OFF_X + (64 + r) * 136 + c * 4) * 4u,
             h + (size_t)(b * 64 + r) * NN + w0 + c * 4);
    }
    if (tid < 128) { sm[T_OFF_WR + tid] = Wread[tid]; sm[T_OFF_RACC + tid] = 0.f; }
    if (tid < 64)  { sm[T_OFF_BL + tid] = blin[tid]; }
    asm volatile("cp.async.commit_group;");
    asm volatile("cp.async.wait_group 0;");
    __syncthreads();

    // ---- tf32 MMA: M=64 (out ch), N=128 (points), K=128 ----
    float acc[2][4][4];
#pragma unroll
    for (int i = 0; i < 2; i++)
#pragma unroll
        for (int j = 0; j < 4; j++)
#pragma unroll
            for (int q = 0; q < 4; q++) acc[i][j][q] = 0.f;

#pragma unroll 1
    for (int ks = 0; ks < 16; ks++) {
        const int k0 = ks * 8;
        uint32_t bf[4][2];
#pragma unroll
        for (int nt = 0; nt < 4; nt++) {
            const int n = wn * 32 + nt * 8 + g;
            bf[nt][0] = f2tf(sm[T_OFF_X + (k0 + t)     * 136 + n]);
            bf[nt][1] = f2tf(sm[T_OFF_X + (k0 + 4 + t) * 136 + n]);
        }
#pragma unroll
        for (int mt = 0; mt < 2; mt++) {
            const int m = wm * 32 + mt * 16 + g;
            uint32_t a0 = f2tf(sm[T_OFF_W + m       * 136 + k0 + t]);
            uint32_t a1 = f2tf(sm[T_OFF_W + (m + 8) * 136 + k0 + t]);
            uint32_t a2 = f2tf(sm[T_OFF_W + m       * 136 + k0 + 4 + t]);
            uint32_t a3 = f2tf(sm[T_OFF_W + (m + 8) * 136 + k0 + 4 + t]);
#pragma unroll
            for (int nt = 0; nt < 4; nt++)
                mma8(acc[mt][nt], a0, a1, a2, a3, bf[nt][0], bf[nt][1]);
        }
    }

    // ---- PReLU + pr stores + racc(pr) partials ----
    const float a = __ldg(pa);
    float* o2 = out2 + (size_t)b * 128 * NN + w0;
    float p[4][2];
#pragma unroll
    for (int nt = 0; nt < 4; nt++) { p[nt][0] = 0.f; p[nt][1] = 0.f; }

#pragma unroll
    for (int mt = 0; mt < 2; mt++) {
#pragma unroll
        for (int q2 = 0; q2 < 2; q2++) {
            const int row = wm * 32 + mt * 16 + g + q2 * 8;
            const float bl = sm[T_OFF_BL + row];
            const float wr = sm[T_OFF_WR + row];
#pragma unroll
            for (int nt = 0; nt < 4; nt++) {
                const int col = wn * 32 + nt * 8 + 2 * t;
                float L0 = acc[mt][nt][q2 * 2 + 0] + bl;
                float L1 = acc[mt][nt][q2 * 2 + 1] + bl;
                float pr0 = L0 >= 0.f ? L0 : a * L0;
                float pr1 = L1 >= 0.f ? L1 : a * L1;
                *reinterpret_cast<float2*>(&o2[(size_t)row * NN + col]) =
                    make_float2(pr0, pr1);
                p[nt][0] += wr * pr0;
                p[nt][1] += wr * pr1;
            }
        }
    }
    // butterfly over g (masks 4,8,16): sum this warp's 32 rows per column
#pragma unroll
    for (int nt = 0; nt < 4; nt++)
#pragma unroll
        for (int i = 0; i < 2; i++) {
            float v = p[nt][i];
            v += __shfl_xor_sync(0xFFFFFFFFu, v, 4);
            v += __shfl_xor_sync(0xFFFFFFFFu, v, 8);
            v += __shfl_xor_sync(0xFFFFFFFFu, v, 16);
            p[nt][i] = v;
        }
    if (g == 0) {
#pragma unroll
        for (int nt = 0; nt < 4; nt++) {
            atomicAdd(&sm[T_OFF_RACC + wn * 32 + nt * 8 + 2 * t],     p[nt][0]);
            atomicAdd(&sm[T_OFF_RACC + wn * 32 + nt * 8 + 2 * t + 1], p[nt][1]);
        }
    }

    // ---- h-copy (exact fp32, from smem) + racc(h) ----
    {
        const int pt = tid & 127;
        const int j0 = (tid >> 7) * 32;
        float rh = 0.f;
#pragma unroll
        for (int j = 0; j < 32; j++) {
            const int row = j0 + j;
            const float v = sm[T_OFF_X + (64 + row) * 136 + pt];
            o2[(size_t)(64 + row) * NN + pt] = v;
            rh += sm[T_OFF_WR + 64 + row] * v;
        }
        atomicAdd(&sm[T_OFF_RACC + pt], rh);
    }
    __syncthreads();
    if (tid < 128)
        out_read[(size_t)b * NN + w0 + tid] = sm[T_OFF_RACC + tid] + __ldg(bread);
}

// ---------------------------------------------------------------------------
extern "C" void kernel_launch(void* const* d_in, const int* in_sizes, int n_in,
                              void* d_out, int out_size) {
    (void)in_sizes; (void)n_in; (void)out_size;
    const float* x     = (const float*)d_in[0];
    const float* h     = (const float*)d_in[1];
    const float* adj   = (const float*)d_in[2];
    const float* Wmlp  = (const float*)d_in[3];
    const float* bmlp  = (const float*)d_in[4];
    const float* Wlin  = (const float*)d_in[5];
    const float* blin  = (const float*)d_in[6];
    const float* Wread = (const float*)d_in[7];
    const float* bread = (const float*)d_in[8];
    const float* pa    = (const float*)d_in[9];

    float* out      = (float*)d_out;
    float* out_read = out;                       // [32, 1, 4096]
    float* out2     = out + (size_t)NB * NN;     // [32, 128, 4096]

    cudaFuncSetAttribute(k2_gemm, cudaFuncAttributeMaxDynamicSharedMemorySize, K2_SMEM);
    cudaFuncSetAttribute(k3_tc,   cudaFuncAttributeMaxDynamicSharedMemorySize, K3_SMEM);

    k0_conv  <<<32768, 256>>>((const float4*)adj);
    k1_buildY<<<dim3(NN / 128, NB), 128>>>(x, h, Wmlp);
    k2_gemm  <<<dim3(NN / 128, MROWS / 128), 256, K2_SMEM>>>(bmlp);
    k3_tc    <<<dim3(NN / 128, NB), 256, K3_SMEM>>>(h, Wlin, blin, Wread, bread, pa,
                                                    out_read, out2);
}

// round 17
// speedup vs baseline: 1.3831x; 1.0617x over previous
#include <cuda_runtime.h>
#include <cuda_bf16.h>
#include <cstdint>

// Problem constants
#define NB   32
#define NN   4096
#define DM   64
#define DIN  65
#define MROWS (NB*DM)      // 2048
#define KDIM  (2*NN)       // 8192

// Scratch (device globals — allocation-free rule)
__device__ __align__(1024) __nv_bfloat16 g_Yb[(size_t)MROWS * KDIM];  // 32 MiB
__device__ __align__(1024) __nv_bfloat16 g_adjb[(size_t)2 * NN * NN]; // 64 MiB
__device__ __align__(1024) float         g_G[(size_t)MROWS * NN];     // 32 MiB (bmlp pre-added)

// ---------------------------------------------------------------------------
// helpers
// ---------------------------------------------------------------------------
__device__ __forceinline__ uint32_t smem_u32(const void* p) {
    uint32_t a;
    asm("{ .reg .u64 t; cvta.to.shared.u64 t, %1; cvt.u32.u64 %0, t; }" : "=r"(a) : "l"(p));
    return a;
}
__device__ __forceinline__ void cp16(uint32_t dst, const void* src) {
    asm volatile("cp.async.cg.shared.global [%0], [%1], 16;" :: "r"(dst), "l"(src));
}
// SW128 swizzle for 128B rows: off ^ ((off>>3)&0x70)
__device__ __forceinline__ uint32_t sw128(uint32_t off) {
    return off ^ ((off >> 3) & 0x70);
}
__device__ __forceinline__ void ldsm4(uint32_t& r0, uint32_t& r1, uint32_t& r2,
                                      uint32_t& r3, uint32_t a) {
    asm volatile("ldmatrix.sync.aligned.m8n8.x4.shared.b16 {%0,%1,%2,%3}, [%4];"
        : "=r"(r0), "=r"(r1), "=r"(r2), "=r"(r3) : "r"(a));
}
__device__ __forceinline__ void mma16(float* d,
    uint32_t a0, uint32_t a1, uint32_t a2, uint32_t a3, uint32_t b0, uint32_t b1) {
    asm volatile("mma.sync.aligned.m16n8k16.row.col.f32.bf16.bf16.f32 "
        "{%0,%1,%2,%3},{%4,%5,%6,%7},{%8,%9},{%0,%1,%2,%3};"
        : "+f"(d[0]), "+f"(d[1]), "+f"(d[2]), "+f"(d[3])
        : "r"(a0), "r"(a1), "r"(a2), "r"(a3), "r"(b0), "r"(b1));
}
// tf32 m16n8k8 mma (layouts verified in R2/R15 kernels)
__device__ __forceinline__ void mma8(float* d,
    uint32_t a0, uint32_t a1, uint32_t a2, uint32_t a3, uint32_t b0, uint32_t b1) {
    asm volatile("mma.sync.aligned.m16n8k8.row.col.f32.tf32.tf32.f32 "
        "{%0,%1,%2,%3},{%4,%5,%6,%7},{%8,%9},{%0,%1,%2,%3};"
        : "+f"(d[0]), "+f"(d[1]), "+f"(d[2]), "+f"(d[3])
        : "r"(a0), "r"(a1), "r"(a2), "r"(a3), "r"(b0), "r"(b1));
}
__device__ __forceinline__ uint32_t f2tf(float f) {
    uint32_t u; asm("cvt.rna.tf32.f32 %0, %1;" : "=r"(u) : "f"(f)); return u;
}

// ---------------------------------------------------------------------------
// K0: adj fp32 -> bf16 (g_adjb)
// ---------------------------------------------------------------------------
__global__ void __launch_bounds__(256) k0_conv(const float4* __restrict__ adj) {
    size_t i = (size_t)blockIdx.x * 256 + threadIdx.x;   // 8,388,608 float4s
    float4 v = adj[i];
    __nv_bfloat162 lo = __float22bfloat162_rn(make_float2(v.x, v.y));
    __nv_bfloat162 hi = __float22bfloat162_rn(make_float2(v.z, v.w));
    uint2 o;
    o.x = *reinterpret_cast<uint32_t*>(&lo);
    o.y = *reinterpret_cast<uint32_t*>(&hi);
    reinterpret_cast<uint2*>(g_adjb)[i] = o;
}

// ---------------------------------------------------------------------------
// K1 (tensor-core): Y[o=(s,m), (b, v)] = W_h @ h + wx ⊗ x, bf16 out.
// M=128 (s,m), K=64 (h channels), N=128 points per CTA; tf32 mma8 with the
// same fragment recipe as k3_tc. x-term folded into the epilogue.
// ---------------------------------------------------------------------------
// dynamic smem layout (floats)
#define Y_OFF_W   0                    // sW[128][72]   (W_h[o][j])
#define Y_OFF_WX  (128*72)             // [128]
#define Y_OFF_X   (Y_OFF_W + 128*72 + 128)   // sX[64][136] (h: [k][n])
#define Y_OFF_SX  (Y_OFF_X + 64*136)   // [128] (x values)
#define Y_FLOATS  (Y_OFF_SX + 128)     // 18176
#define K1_SMEM   (Y_FLOATS * 4)       // 72704 bytes

__global__ void __launch_bounds__(256, 2) k1_tc(
    const float* __restrict__ x, const float* __restrict__ h,
    const float* __restrict__ Wmlp)
{
    extern __shared__ float sm[];
    const uint32_t sbase = smem_u32(sm);
    const int tid  = threadIdx.x;
    const int lane = tid & 31, warp = tid >> 5;
    const int g = lane >> 2, t = lane & 3;
    const int wm = warp >> 2, wn = warp & 3;    // 2x4 warp grid over 128 x 128
    const int b  = blockIdx.y;
    const int w0 = blockIdx.x * 128;

    // stage W_h (rearranged) + wx
    for (int idx = tid; idx < 128 * 64; idx += 256) {
        int o = idx >> 6, j = idx & 63;
        sm[Y_OFF_W + o * 72 + j] = Wmlp[(o & 63) * 130 + (o >> 6) * 65 + 1 + j];
    }
    if (tid < 128) sm[Y_OFF_WX + tid] = Wmlp[(tid & 63) * 130 + (tid >> 6) * 65];
    else           sm[Y_OFF_SX + tid - 128] = x[(size_t)b * NN + w0 + tid - 128];
    // stage h tile [64 k][128 n] via cp.async
#pragma unroll
    for (int i = 0; i < 8; i++) {
        int idx = i * 256 + tid;
        int r = idx >> 5, c = idx & 31;
        cp16(sbase + (uint32_t)(Y_OFF_X + r * 136 + c * 4) * 4u,
             h + (size_t)(b * 64 + r) * NN + w0 + c * 4);
    }
    asm volatile("cp.async.commit_group;");
    asm volatile("cp.async.wait_group 0;");
    __syncthreads();

    float acc[4][4][4];
#pragma unroll
    for (int i = 0; i < 4; i++)
#pragma unroll
        for (int j = 0; j < 4; j++)
#pragma unroll
            for (int q = 0; q < 4; q++) acc[i][j][q] = 0.f;

#pragma unroll 1
    for (int ks = 0; ks < 8; ks++) {
        const int k0 = ks * 8;
        uint32_t bf[4][2];
#pragma unroll
        for (int nt = 0; nt < 4; nt++) {
            const int n = wn * 32 + nt * 8 + g;
            bf[nt][0] = f2tf(sm[Y_OFF_X + (k0 + t)     * 136 + n]);
            bf[nt][1] = f2tf(sm[Y_OFF_X + (k0 + 4 + t) * 136 + n]);
        }
#pragma unroll
        for (int mt = 0; mt < 4; mt++) {
            const int m = wm * 64 + mt * 16 + g;
            uint32_t a0 = f2tf(sm[Y_OFF_W + m       * 72 + k0 + t]);
            uint32_t a1 = f2tf(sm[Y_OFF_W + (m + 8) * 72 + k0 + t]);
            uint32_t a2 = f2tf(sm[Y_OFF_W + m       * 72 + k0 + 4 + t]);
            uint32_t a3 = f2tf(sm[Y_OFF_W + (m + 8) * 72 + k0 + 4 + t]);
#pragma unroll
            for (int nt = 0; nt < 4; nt++)
                mma8(acc[mt][nt], a0, a1, a2, a3, bf[nt][0], bf[nt][1]);
        }
    }

    // epilogue: += wx[row]*x[col], cvt bf16x2, store to g_Yb
#pragma unroll
    for (int mt = 0; mt < 4; mt++) {
#pragma unroll
        for (int q2 = 0; q2 < 2; q2++) {
            const int row = wm * 64 + mt * 16 + g + q2 * 8;   // o = s*64+m
            const float wx = sm[Y_OFF_WX + row];
            __nv_bfloat16* dst = g_Yb + (size_t)(b * 64 + (row & 63)) * KDIM
                               + (size_t)(row >> 6) * NN + w0;
#pragma unroll
            for (int nt = 0; nt < 4; nt++) {
                const int col = wn * 32 + nt * 8 + 2 * t;
                float v0 = acc[mt][nt][q2 * 2 + 0] + wx * sm[Y_OFF_SX + col];
                float v1 = acc[mt][nt][q2 * 2 + 1] + wx * sm[Y_OFF_SX + col + 1];
                __nv_bfloat162 p = __float22bfloat162_rn(make_float2(v0, v1));
                *reinterpret_cast<uint32_t*>(dst + col) =
                    *reinterpret_cast<uint32_t*>(&p);
            }
        }
    }
}

// ---------------------------------------------------------------------------
// K2: G[2048,4096] = Y @ A   (bf16 mma.sync.m16n8k16 + ldmatrix)
// CTA tile 64x128x64 (1024 CTAs -> ~1.5% wave-tail imbalance vs 15% at 512),
// 3-stage cp.async ring, 8 warps (2x4), warp tile 32x32.
// Stores G + bmlp[m] (bias folded here, exact fp32).
// ---------------------------------------------------------------------------
#define STAGES      3
#define A_BYTES     8192            // 64 rows x 128B (k=64 bf16), SW128
#define B_BYTES     16384           // 128 rows x 128B
#define STAGE_BYTES (A_BYTES + B_BYTES)
#define K2_SMEM     (STAGES * STAGE_BYTES)   // 73728

__global__ void __launch_bounds__(256, 2) k2_gemm(const float* __restrict__ bmlp)
{
    extern __shared__ char smem[];
    __shared__ float sbm[64];
    const uint32_t sbase = smem_u32(smem);
    const int tid  = threadIdx.x;
    const int lane = tid & 31, warp = tid >> 5;
    const int wm = warp >> 2, wn = warp & 3;        // 2 x 4 warp grid
    const int bx = blockIdx.x, by = blockIdx.y;
    const int m0 = by * 64, n0 = bx * 128;

    if (tid < 64) sbm[tid] = bmlp[tid];

    // fragment-load lane geometry (ldmatrix.x4, no trans; TN k-major tiles)
    const int alrow = (lane & 7) + ((lane >> 3) & 1) * 8;   // A: {m0-7,m8-15}x{k0,k16}
    const int akb   = (lane >> 4) * 16;
    const int blrow = (lane & 7) + ((lane >> 4) << 3);      // B: {n0-7},{n8-15} x {klo,khi}
    const int bkb   = ((lane >> 3) & 1) * 16;
    const int xorm  = (lane & 7) << 4;                      // swizzle XOR (row&7)<<4

    float acc[2][4][4];
#pragma unroll
    for (int i = 0; i < 2; i++)
#pragma unroll
        for (int j = 0; j < 4; j++)
#pragma unroll
            for (int q = 0; q < 4; q++) acc[i][j][q] = 0.f;

    auto load_stage = [&](int st, int k) {
        const int k0 = k << 6;
        const int ssel = k0 >> 12, kv = k0 & (NN - 1);
        const uint32_t abase = sbase + st * STAGE_BYTES;
        const uint32_t bbase = abase + A_BYTES;
#pragma unroll
        for (int i = 0; i < 2; i++) {                  // A: 64 rows x 8 x 16B
            int c = i * 256 + tid;
            int row = c >> 3, col = c & 7;
            cp16(abase + sw128(row * 128 + col * 16),
                 g_Yb + (size_t)(m0 + row) * KDIM + k0 + col * 8);
        }
#pragma unroll
        for (int i = 0; i < 4; i++) {                  // B: 128 rows x 8 x 16B
            int c = i * 256 + tid;
            int row = c >> 3, col = c & 7;
            cp16(bbase + sw128(row * 128 + col * 16),
                 g_adjb + (size_t)ssel * NN * NN + (size_t)(n0 + row) * NN + kv + col * 8);
        }
    };

    load_stage(0, 0); asm volatile("cp.async.commit_group;");
    load_stage(1, 1); asm volatile("cp.async.commit_group;");

    const int NSTEP = KDIM / 64;   // 128
#pragma unroll 1
    for (int k = 0; k < NSTEP; k++) {
        asm volatile("cp.async.wait_group 1;");
        __syncthreads();

        // Issue next-stage loads FIRST: stage (k+2)%3 was last read at iter
        // k-1, which the barrier above already ordered.
        const int kn = k + 2;
        if (kn < NSTEP) load_stage(kn % STAGES, kn);
        asm volatile("cp.async.commit_group;");

        const int st = k % STAGES;
        const uint32_t sA = sbase + st * STAGE_BYTES;
        const uint32_t sB = sA + A_BYTES;
        const uint32_t aBase = sA + (uint32_t)(wm * 32 + alrow) * 128;
        const uint32_t bBase = sB + (uint32_t)(wn * 32 + blrow) * 128;

#pragma unroll
        for (int ks = 0; ks < 4; ks++) {
            const int kb = ks * 32;
            uint32_t bf[4][2];
#pragma unroll
            for (int j = 0; j < 2; j++) {
                uint32_t r0, r1, r2, r3;
                ldsm4(r0, r1, r2, r3,
                      bBase + (uint32_t)(j * 16) * 128 + ((kb + bkb) ^ xorm));
                bf[2*j][0] = r0;   bf[2*j][1] = r1;
                bf[2*j+1][0] = r2; bf[2*j+1][1] = r3;
            }
#pragma unroll
            for (int mt = 0; mt < 2; mt++) {
                uint32_t a0, a1, a2, a3;
                ldsm4(a0, a1, a2, a3,
                      aBase + (uint32_t)(mt * 16) * 128 + ((kb + akb) ^ xorm));
#pragma unroll
                for (int nt = 0; nt < 4; nt++)
                    mma16(acc[mt][nt], a0, a1, a2, a3, bf[nt][0], bf[nt][1]);
            }
        }
    }

    // Store C tile -> g_G (+ bmlp bias, folded exactly in fp32)
    const int g = lane >> 2, t = lane & 3;
#pragma unroll
    for (int mt = 0; mt < 2; mt++) {
        const int row = m0 + wm * 32 + mt * 16 + g;
        const float b0 = sbm[row & 63], b1 = sbm[(row + 8) & 63];
#pragma unroll
        for (int nt = 0; nt < 4; nt++) {
            const int col = n0 + wn * 32 + nt * 8 + 2 * t;
            float2 v0 = make_float2(acc[mt][nt][0] + b0, acc[mt][nt][1] + b0);
            float2 v1 = make_float2(acc[mt][nt][2] + b1, acc[mt][nt][3] + b1);
            *reinterpret_cast<float2*>(&g_G[(size_t)row       * NN + col]) = v0;
            *reinterpret_cast<float2*>(&g_G[(size_t)(row + 8) * NN + col]) = v1;
        }
    }
}

// ---------------------------------------------------------------------------
// K3: tensor-core epilogue. lin[64, pts] = Wlin(tf32) @ Xcat(tf32)[128, pts],
// Xcat = [G'(fp32, bmlp folded); h]. PReLU, out2 = [pr; h], out_read.
// ---------------------------------------------------------------------------
// dynamic smem layout (floats); row stride 136 words (mod 32 == 8)
#define T_OFF_W    0                       // sW[64][136]
#define T_OFF_X    (64*136)                // sX[128][136]: rows 0-63 G, 64-127 h
#define T_OFF_RACC (T_OFF_X + 128*136)     // [128]
#define T_OFF_WR   (T_OFF_RACC + 128)      // [128]
#define T_OFF_BL   (T_OFF_WR + 128)        // [64]
#define T_FLOATS   (T_OFF_BL + 64)         // 26432
#define K3_SMEM    (T_FLOATS * 4)          // 105728 bytes

__global__ void __launch_bounds__(256, 2) k3_tc(
    const float* __restrict__ h,    const float* __restrict__ Wlin,
    const float* __restrict__ blin,
    const float* __restrict__ Wread,const float* __restrict__ bread,
    const float* __restrict__ pa,
    float* __restrict__ out_read,   float* __restrict__ out2)
{
    extern __shared__ float sm[];
    const uint32_t sbase = smem_u32(sm);
    const int tid  = threadIdx.x;
    const int lane = tid & 31, warp = tid >> 5;
    const int g = lane >> 2, t = lane & 3;
    const int wm = warp >> 2, wn = warp & 3;     // 2 x 4 warp grid over 64 x 128
    const int b  = blockIdx.y;
    const int w0 = blockIdx.x * 128;

    // ---- stage W, G, h via cp.async; scalars via plain stores ----
#pragma unroll
    for (int i = 0; i < 8; i++) {                 // W: 64 rows x 32 chunks
        int idx = i * 256 + tid;
        int m = idx >> 5, c = idx & 31;
        cp16(sbase + (uint32_t)(T_OFF_W + m * 136 + c * 4) * 4u,
             Wlin + m * 128 + c * 4);
    }
#pragma unroll
    for (int i = 0; i < 8; i++) {                 // X rows 0-63: G'
        int idx = i * 256 + tid;
        int r = idx >> 5, c = idx & 31;
        cp16(sbase + (uint32_t)(T_OFF_X + r * 136 + c * 4) * 4u,
             g_G + (size_t)(b * 64 + r) * NN + w0 + c * 4);
    }
#pragma unroll
    for (int i = 0; i < 8; i++) {                 // X rows 64-127: h
        int idx = i * 256 + tid;
        int r = idx >> 5, c = idx & 31;
        cp16(sbase + (uint32_t)(T_OFF_X + (64 + r) * 136 + c * 4) * 4u,
             h + (size_t)(b * 64 + r) * NN + w0 + c * 4);
    }
    if (tid < 128) { sm[T_OFF_WR + tid] = Wread[tid]; sm[T_OFF_RACC + tid] = 0.f; }
    if (tid < 64)  { sm[T_OFF_BL + tid] = blin[tid]; }
    asm volatile("cp.async.commit_group;");
    asm volatile("cp.async.wait_group 0;");
    __syncthreads();

    // ---- tf32 MMA: M=64 (out ch), N=128 (points), K=128 ----
    float acc[2][4][4];
#pragma unroll
    for (int i = 0; i < 2; i++)
#pragma unroll
        for (int j = 0; j < 4; j++)
#pragma unroll
            for (int q = 0; q < 4; q++) acc[i][j][q] = 0.f;

#pragma unroll 1
    for (int ks = 0; ks < 16; ks++) {
        const int k0 = ks * 8;
        uint32_t bf[4][2];
#pragma unroll
        for (int nt = 0; nt < 4; nt++) {
            const int n = wn * 32 + nt * 8 + g;
            bf[nt][0] = f2tf(sm[T_OFF_X + (k0 + t)     * 136 + n]);
            bf[nt][1] = f2tf(sm[T_OFF_X + (k0 + 4 + t) * 136 + n]);
        }
#pragma unroll
        for (int mt = 0; mt < 2; mt++) {
            const int m = wm * 32 + mt * 16 + g;
            uint32_t a0 = f2tf(sm[T_OFF_W + m       * 136 + k0 + t]);
            uint32_t a1 = f2tf(sm[T_OFF_W + (m + 8) * 136 + k0 + t]);
            uint32_t a2 = f2tf(sm[T_OFF_W + m       * 136 + k0 + 4 + t]);
            uint32_t a3 = f2tf(sm[T_OFF_W + (m + 8) * 136 + k0 + 4 + t]);
#pragma unroll
            for (int nt = 0; nt < 4; nt++)
                mma8(acc[mt][nt], a0, a1, a2, a3, bf[nt][0], bf[nt][1]);
        }
    }

    // ---- PReLU + pr stores + racc(pr) partials ----
    const float a = __ldg(pa);
    float* o2 = out2 + (size_t)b * 128 * NN + w0;
    float p[4][2];
#pragma unroll
    for (int nt = 0; nt < 4; nt++) { p[nt][0] = 0.f; p[nt][1] = 0.f; }

#pragma unroll
    for (int mt = 0; mt < 2; mt++) {
#pragma unroll
        for (int q2 = 0; q2 < 2; q2++) {
            const int row = wm * 32 + mt * 16 + g + q2 * 8;
            const float bl = sm[T_OFF_BL + row];
            const float wr = sm[T_OFF_WR + row];
#pragma unroll
            for (int nt = 0; nt < 4; nt++) {
                const int col = wn * 32 + nt * 8 + 2 * t;
                float L0 = acc[mt][nt][q2 * 2 + 0] + bl;
                float L1 = acc[mt][nt][q2 * 2 + 1] + bl;
                float pr0 = L0 >= 0.f ? L0 : a * L0;
                float pr1 = L1 >= 0.f ? L1 : a * L1;
                *reinterpret_cast<float2*>(&o2[(size_t)row * NN + col]) =
                    make_float2(pr0, pr1);
                p[nt][0] += wr * pr0;
                p[nt][1] += wr * pr1;
            }
        }
    }
    // butterfly over g (masks 4,8,16): sum this warp's 32 rows per column
#pragma unroll
    for (int nt = 0; nt < 4; nt++)
#pragma unroll
        for (int i = 0; i < 2; i++) {
            float v = p[nt][i];
            v += __shfl_xor_sync(0xFFFFFFFFu, v, 4);
            v += __shfl_xor_sync(0xFFFFFFFFu, v, 8);
            v += __shfl_xor_sync(0xFFFFFFFFu, v, 16);
            p[nt][i] = v;
        }
    if (g == 0) {
#pragma unroll
        for (int nt = 0; nt < 4; nt++) {
            atomicAdd(&sm[T_OFF_RACC + wn * 32 + nt * 8 + 2 * t],     p[nt][0]);
            atomicAdd(&sm[T_OFF_RACC + wn * 32 + nt * 8 + 2 * t + 1], p[nt][1]);
        }
    }

    // ---- h-copy (exact fp32, from smem) + racc(h) ----
    {
        const int pt = tid & 127;
        const int j0 = (tid >> 7) * 32;
        float rh = 0.f;
#pragma unroll
        for (int j = 0; j < 32; j++) {
            const int row = j0 + j;
            const float v = sm[T_OFF_X + (64 + row) * 136 + pt];
            o2[(size_t)(64 + row) * NN + pt] = v;
            rh += sm[T_OFF_WR + 64 + row] * v;
        }
        atomicAdd(&sm[T_OFF_RACC + pt], rh);
    }
    __syncthreads();
    if (tid < 128)
        out_read[(size_t)b * NN + w0 + tid] = sm[T_OFF_RACC + tid] + __ldg(bread);
}

// ---------------------------------------------------------------------------
extern "C" void kernel_launch(void* const* d_in, const int* in_sizes, int n_in,
                              void* d_out, int out_size) {
    (void)in_sizes; (void)n_in; (void)out_size;
    const float* x     = (const float*)d_in[0];
    const float* h     = (const float*)d_in[1];
    const float* adj   = (const float*)d_in[2];
    const float* Wmlp  = (const float*)d_in[3];
    const float* bmlp  = (const float*)d_in[4];
    const float* Wlin  = (const float*)d_in[5];
    const float* blin  = (const float*)d_in[6];
    const float* Wread = (const float*)d_in[7];
    const float* bread = (const float*)d_in[8];
    const float* pa    = (const float*)d_in[9];

    float* out      = (float*)d_out;
    float* out_read = out;                       // [32, 1, 4096]
    float* out2     = out + (size_t)NB * NN;     // [32, 128, 4096]

    cudaFuncSetAttribute(k1_tc,   cudaFuncAttributeMaxDynamicSharedMemorySize, K1_SMEM);
    cudaFuncSetAttribute(k2_gemm, cudaFuncAttributeMaxDynamicSharedMemorySize, K2_SMEM);
    cudaFuncSetAttribute(k3_tc,   cudaFuncAttributeMaxDynamicSharedMemorySize, K3_SMEM);

    k0_conv  <<<32768, 256>>>((const float4*)adj);
    k1_tc    <<<dim3(NN / 128, NB), 256, K1_SMEM>>>(x, h, Wmlp);
    k2_gemm  <<<dim3(NN / 128, MROWS / 64), 256, K2_SMEM>>>(bmlp);
    k3_tc    <<<dim3(NN / 128, NB), 256, K3_SMEM>>>(h, Wlin, blin, Wread, bread, pa,
                                                    out_read, out2);
}